// round 3
// baseline (speedup 1.0000x reference)
#include <cuda_runtime.h>
#include <cuda_bf16.h>
#include <stdint.h>
#include <math.h>

// Problem constants
#define Bn  64
#define Sn  512
#define INn 512
#define Hn  1024
#define G3  3072          // 3*H
#define SB  32768         // S*B
#define NBLK 96           // persistent-kernel grid (2 dirs x 48 N-tiles)

// ----------------------------------------------------------------------------
// Device scratch (static — no allocations allowed)
// ----------------------------------------------------------------------------
__device__ float g_xT[(size_t)SB * INn];
__device__ float g_gi[(size_t)2 * SB * G3];
__device__ float g_h0seq[(size_t)2 * SB * Hn];
__device__ float g_gh[2 * Bn * G3];
__device__ float g_hcur[2 * Bn * Hn];
__device__ float g_bias0[2 * G3];
__device__ float g_bias1[2 * G3];

__device__ __nv_bfloat16 g_wih0_hi[(size_t)2 * G3 * INn];
__device__ __nv_bfloat16 g_wih0_lo[(size_t)2 * G3 * INn];
__device__ __nv_bfloat16 g_whh0_hi[(size_t)2 * G3 * Hn];
__device__ __nv_bfloat16 g_whh0_lo[(size_t)2 * G3 * Hn];
__device__ __nv_bfloat16 g_wih1_hi[(size_t)2 * G3 * Hn];
__device__ __nv_bfloat16 g_wih1_lo[(size_t)2 * G3 * Hn];
__device__ __nv_bfloat16 g_whh1_hi[(size_t)2 * G3 * Hn];
__device__ __nv_bfloat16 g_whh1_lo[(size_t)2 * G3 * Hn];

// grid barrier state
__device__ volatile unsigned g_bar_gen;
__device__ unsigned g_bar_cnt;

// ----------------------------------------------------------------------------
// Prep kernels
// ----------------------------------------------------------------------------
__global__ void k_xT(const float* __restrict__ x, float* __restrict__ xT) {
    size_t total = (size_t)Bn * Sn * INn;
    for (size_t i = (size_t)blockIdx.x * blockDim.x + threadIdx.x; i < total;
         i += (size_t)gridDim.x * blockDim.x) {
        int k = (int)(i % INn);
        size_t tmp = i / INn;
        int s = (int)(tmp % Sn);
        int b = (int)(tmp / Sn);
        xT[((size_t)s * Bn + b) * INn + k] = x[i];
    }
}

__global__ void k_split(const float* __restrict__ src, __nv_bfloat16* __restrict__ hi,
                        __nv_bfloat16* __restrict__ lo, int n) {
    for (int i = blockIdx.x * blockDim.x + threadIdx.x; i < n;
         i += gridDim.x * blockDim.x) {
        float v = src[i];
        __nv_bfloat16 h = __float2bfloat16(v);
        hi[i] = h;
        lo[i] = __float2bfloat16(v - __bfloat162float(h));
    }
}

__global__ void k_split_rev(const float* __restrict__ src, __nv_bfloat16* __restrict__ hi,
                            __nv_bfloat16* __restrict__ lo, int N, int K) {
    int total = N * K;
    for (int i = blockIdx.x * blockDim.x + threadIdx.x; i < total;
         i += gridDim.x * blockDim.x) {
        int n = i / K;
        int k = i % K;
        float v = src[(size_t)n * K + (K - 1 - k)];
        __nv_bfloat16 h = __float2bfloat16(v);
        hi[i] = h;
        lo[i] = __float2bfloat16(v - __bfloat162float(h));
    }
}

__global__ void k_bias(const float* __restrict__ bih, const float* __restrict__ bhh,
                       float* __restrict__ dst) {
    int n = blockIdx.x * blockDim.x + threadIdx.x;
    if (n < G3) dst[n] = bih[n] + (n < 2 * Hn ? bhh[n] : 0.0f);
}

// ----------------------------------------------------------------------------
// MMA helper
// ----------------------------------------------------------------------------
__device__ __forceinline__ void mma_bf16(float c[4], const uint32_t a[4],
                                         uint32_t b0, uint32_t b1) {
    asm("mma.sync.aligned.m16n8k16.row.col.f32.bf16.bf16.f32 "
        "{%0,%1,%2,%3}, {%4,%5,%6,%7}, {%8,%9}, {%0,%1,%2,%3};\n"
        : "+f"(c[0]), "+f"(c[1]), "+f"(c[2]), "+f"(c[3])
        : "r"(a[0]), "r"(a[1]), "r"(a[2]), "r"(a[3]), "r"(b0), "r"(b1));
}

// ----------------------------------------------------------------------------
// Batched split-bf16 GEMM: C[M,N] = A[M,K] * W[N,K]^T (+bias), per-z operands
// ----------------------------------------------------------------------------
__global__ __launch_bounds__(256) void k_gemm(
    const float* __restrict__ A, size_t aStrZ,
    const __nv_bfloat16* __restrict__ Whi, const __nv_bfloat16* __restrict__ Wlo,
    size_t wStrZ,
    const float* __restrict__ bias, size_t bStrZ,
    float* __restrict__ C, size_t cStrZ,
    int N, int K)
{
    const int z = blockIdx.z;
    A   += (size_t)z * aStrZ;
    Whi += (size_t)z * wStrZ;
    Wlo += (size_t)z * wStrZ;
    const float* biasz = bias ? (bias + (size_t)z * bStrZ) : nullptr;
    C   += (size_t)z * cStrZ;

    const int m0 = blockIdx.y * 64;
    const int n0 = blockIdx.x * 64;

    __shared__ __align__(16) __nv_bfloat16 sA[2][64][40];
    __shared__ __align__(16) __nv_bfloat16 sW[2][64][40];

    const int tid  = threadIdx.x;
    const int lane = tid & 31;
    const int warp = tid >> 5;
    const int wm = warp & 3;
    const int wn = warp >> 2;
    const int g  = lane >> 2;
    const int tq = lane & 3;

    float acc[4][4];
#pragma unroll
    for (int i = 0; i < 4; i++)
#pragma unroll
        for (int j = 0; j < 4; j++) acc[i][j] = 0.0f;

    const int wrow  = tid >> 2;
    const int wpart = tid & 3;

    for (int k0 = 0; k0 < K; k0 += 32) {
#pragma unroll
        for (int r = 0; r < 4; r++) {
            int idx = tid + 256 * r;
            int row = idx >> 4;
            int cp  = idx & 15;
            float2 v = *reinterpret_cast<const float2*>(
                A + (size_t)(m0 + row) * K + (k0 + cp * 2));
            __nv_bfloat16 h0 = __float2bfloat16(v.x);
            __nv_bfloat16 h1 = __float2bfloat16(v.y);
            __nv_bfloat16 l0 = __float2bfloat16(v.x - __bfloat162float(h0));
            __nv_bfloat16 l1 = __float2bfloat16(v.y - __bfloat162float(h1));
            *reinterpret_cast<__nv_bfloat162*>(&sA[0][row][cp * 2]) =
                __halves2bfloat162(h0, h1);
            *reinterpret_cast<__nv_bfloat162*>(&sA[1][row][cp * 2]) =
                __halves2bfloat162(l0, l1);
        }
        {
            const size_t off = (size_t)(n0 + wrow) * K + k0 + wpart * 8;
            *reinterpret_cast<uint4*>(&sW[0][wrow][wpart * 8]) =
                *reinterpret_cast<const uint4*>(Whi + off);
            *reinterpret_cast<uint4*>(&sW[1][wrow][wpart * 8]) =
                *reinterpret_cast<const uint4*>(Wlo + off);
        }
        __syncthreads();

#pragma unroll
        for (int kk = 0; kk < 32; kk += 16) {
            const int ar = wm * 16 + g;
            const int ac = kk + tq * 2;
            uint32_t ah[4], al[4];
            ah[0] = *reinterpret_cast<const uint32_t*>(&sA[0][ar    ][ac    ]);
            ah[1] = *reinterpret_cast<const uint32_t*>(&sA[0][ar + 8][ac    ]);
            ah[2] = *reinterpret_cast<const uint32_t*>(&sA[0][ar    ][ac + 8]);
            ah[3] = *reinterpret_cast<const uint32_t*>(&sA[0][ar + 8][ac + 8]);
            al[0] = *reinterpret_cast<const uint32_t*>(&sA[1][ar    ][ac    ]);
            al[1] = *reinterpret_cast<const uint32_t*>(&sA[1][ar + 8][ac    ]);
            al[2] = *reinterpret_cast<const uint32_t*>(&sA[1][ar    ][ac + 8]);
            al[3] = *reinterpret_cast<const uint32_t*>(&sA[1][ar + 8][ac + 8]);
#pragma unroll
            for (int nf = 0; nf < 4; nf++) {
                const int br = wn * 32 + nf * 8 + g;
                uint32_t bh0 = *reinterpret_cast<const uint32_t*>(&sW[0][br][ac    ]);
                uint32_t bh1 = *reinterpret_cast<const uint32_t*>(&sW[0][br][ac + 8]);
                uint32_t bl0 = *reinterpret_cast<const uint32_t*>(&sW[1][br][ac    ]);
                uint32_t bl1 = *reinterpret_cast<const uint32_t*>(&sW[1][br][ac + 8]);
                mma_bf16(acc[nf], ah, bh0, bh1);
                mma_bf16(acc[nf], ah, bl0, bl1);
                mma_bf16(acc[nf], al, bh0, bh1);
            }
        }
        __syncthreads();
    }

#pragma unroll
    for (int nf = 0; nf < 4; nf++) {
        int col = n0 + wn * 32 + nf * 8 + tq * 2;
        float b0 = biasz ? biasz[col]     : 0.0f;
        float b1 = biasz ? biasz[col + 1] : 0.0f;
        int row = m0 + wm * 16 + g;
        float* c0 = C + (size_t)row * N + col;
        c0[0] = acc[nf][0] + b0;
        c0[1] = acc[nf][1] + b1;
        float* c1 = C + (size_t)(row + 8) * N + col;
        c1[0] = acc[nf][2] + b0;
        c1[1] = acc[nf][3] + b1;
    }
}

// ----------------------------------------------------------------------------
// Software grid barrier (all NBLK blocks co-resident)
// ----------------------------------------------------------------------------
__device__ __forceinline__ void grid_barrier() {
    __syncthreads();
    if (threadIdx.x == 0) {
        unsigned gen = g_bar_gen;       // volatile read BEFORE arriving
        __threadfence();
        if (atomicAdd(&g_bar_cnt, 1) == NBLK - 1) {
            g_bar_cnt = 0;
            __threadfence();
            g_bar_gen = gen + 1;        // release
        } else {
            while (g_bar_gen == gen) { __nanosleep(64); }
        }
        __threadfence();                // acquire
    }
    __syncthreads();
}

// ----------------------------------------------------------------------------
// Persistent recurrence kernel: 512 GRU steps for one layer, both directions.
// Grid: 96 blocks = 2 dirs x 48 N-tiles (64 cols each). 256 threads.
// ----------------------------------------------------------------------------
__global__ __launch_bounds__(256) void k_recur(
    const __nv_bfloat16* __restrict__ Whi,  // [2][G3][Hn]
    const __nv_bfloat16* __restrict__ Wlo,
    const float* __restrict__ gi,           // [2][SB][G3]
    float* __restrict__ gh,                 // [2][B][G3]
    float* __restrict__ hcur,               // [2][B][H]
    const float* __restrict__ bhh_f, const float* __restrict__ bhh_b,
    float* __restrict__ h0seq,              // [2][SB][H] or null
    float* __restrict__ out)                // or null
{
    const int tid  = threadIdx.x;
    const int dir  = blockIdx.x / 48;
    const int n0   = (blockIdx.x % 48) * 64;

    const __nv_bfloat16* WhiD = Whi + (size_t)dir * G3 * Hn;
    const __nv_bfloat16* WloD = Wlo + (size_t)dir * G3 * Hn;
    const float* AhD = hcur + (size_t)dir * Bn * Hn;
    float* ghD = gh + (size_t)dir * Bn * G3;

    __shared__ __align__(16) __nv_bfloat16 sA[2][64][40];
    __shared__ __align__(16) __nv_bfloat16 sW[2][64][40];

    const int lane = tid & 31;
    const int warp = tid >> 5;
    const int wm = warp & 3;
    const int wn = warp >> 2;
    const int g  = lane >> 2;
    const int tq = lane & 3;
    const int wrow  = tid >> 2;
    const int wpart = tid & 3;

    // zero hcur
    for (int i = blockIdx.x * 256 + tid; i < 2 * Bn * Hn; i += NBLK * 256)
        hcur[i] = 0.0f;
    grid_barrier();

    for (int t = 0; t < Sn; ++t) {
        // ---- GEMM phase: gh_tile = hcur[dir] (64x1024) x Whh[dir][n0:n0+64]^T
        float acc[4][4];
#pragma unroll
        for (int i = 0; i < 4; i++)
#pragma unroll
            for (int j = 0; j < 4; j++) acc[i][j] = 0.0f;

        for (int k0 = 0; k0 < Hn; k0 += 32) {
#pragma unroll
            for (int r = 0; r < 4; r++) {
                int idx = tid + 256 * r;
                int row = idx >> 4;
                int cp  = idx & 15;
                float2 v = *reinterpret_cast<const float2*>(
                    AhD + (size_t)row * Hn + (k0 + cp * 2));
                __nv_bfloat16 h0 = __float2bfloat16(v.x);
                __nv_bfloat16 h1 = __float2bfloat16(v.y);
                __nv_bfloat16 l0 = __float2bfloat16(v.x - __bfloat162float(h0));
                __nv_bfloat16 l1 = __float2bfloat16(v.y - __bfloat162float(h1));
                *reinterpret_cast<__nv_bfloat162*>(&sA[0][row][cp * 2]) =
                    __halves2bfloat162(h0, h1);
                *reinterpret_cast<__nv_bfloat162*>(&sA[1][row][cp * 2]) =
                    __halves2bfloat162(l0, l1);
            }
            {
                const size_t off = (size_t)(n0 + wrow) * Hn + k0 + wpart * 8;
                *reinterpret_cast<uint4*>(&sW[0][wrow][wpart * 8]) =
                    *reinterpret_cast<const uint4*>(WhiD + off);
                *reinterpret_cast<uint4*>(&sW[1][wrow][wpart * 8]) =
                    *reinterpret_cast<const uint4*>(WloD + off);
            }
            __syncthreads();

#pragma unroll
            for (int kk = 0; kk < 32; kk += 16) {
                const int ar = wm * 16 + g;
                const int ac = kk + tq * 2;
                uint32_t ah[4], al[4];
                ah[0] = *reinterpret_cast<const uint32_t*>(&sA[0][ar    ][ac    ]);
                ah[1] = *reinterpret_cast<const uint32_t*>(&sA[0][ar + 8][ac    ]);
                ah[2] = *reinterpret_cast<const uint32_t*>(&sA[0][ar    ][ac + 8]);
                ah[3] = *reinterpret_cast<const uint32_t*>(&sA[0][ar + 8][ac + 8]);
                al[0] = *reinterpret_cast<const uint32_t*>(&sA[1][ar    ][ac    ]);
                al[1] = *reinterpret_cast<const uint32_t*>(&sA[1][ar + 8][ac    ]);
                al[2] = *reinterpret_cast<const uint32_t*>(&sA[1][ar    ][ac + 8]);
                al[3] = *reinterpret_cast<const uint32_t*>(&sA[1][ar + 8][ac + 8]);
#pragma unroll
                for (int nf = 0; nf < 4; nf++) {
                    const int br = wn * 32 + nf * 8 + g;
                    uint32_t bh0 = *reinterpret_cast<const uint32_t*>(&sW[0][br][ac    ]);
                    uint32_t bh1 = *reinterpret_cast<const uint32_t*>(&sW[0][br][ac + 8]);
                    uint32_t bl0 = *reinterpret_cast<const uint32_t*>(&sW[1][br][ac    ]);
                    uint32_t bl1 = *reinterpret_cast<const uint32_t*>(&sW[1][br][ac + 8]);
                    mma_bf16(acc[nf], ah, bh0, bh1);
                    mma_bf16(acc[nf], ah, bl0, bl1);
                    mma_bf16(acc[nf], al, bh0, bh1);
                }
            }
            __syncthreads();
        }

        // write gh tile
#pragma unroll
        for (int nf = 0; nf < 4; nf++) {
            int col = n0 + wn * 32 + nf * 8 + tq * 2;
            int row = wm * 16 + g;
            float* c0 = ghD + (size_t)row * G3 + col;
            c0[0] = acc[nf][0];
            c0[1] = acc[nf][1];
            float* c1 = ghD + (size_t)(row + 8) * G3 + col;
            c1[0] = acc[nf][2];
            c1[1] = acc[nf][3];
        }

        grid_barrier();

        // ---- gate phase: grid-strided over 2*B*H
        for (int idx = blockIdx.x * 256 + tid; idx < 2 * Bn * Hn; idx += NBLK * 256) {
            int d   = idx >> 16;            // Bn*Hn = 65536
            int rem = idx & 65535;
            int b   = rem >> 10;
            int j   = rem & (Hn - 1);

            const float* giD = gi + (size_t)d * SB * G3 + ((size_t)t * Bn + b) * G3;
            const float* ghd = gh + (size_t)d * Bn * G3 + (size_t)b * G3;
            const float* bhh = d ? bhh_b : bhh_f;

            float ir  = giD[j];
            float iz  = giD[Hn + j];
            float inn = giD[2 * Hn + j];
            float hr  = ghd[j];
            float hz  = ghd[Hn + j];
            float hn  = ghd[2 * Hn + j] + bhh[2 * Hn + j];
            float h   = hcur[(size_t)d * Bn * Hn + rem];

            float r  = 1.0f / (1.0f + expf(-(ir + hr)));
            float zz = 1.0f / (1.0f + expf(-(iz + hz)));
            float n  = tanhf(inn + r * hn);
            float hnew = (1.0f - zz) * n + zz * h;

            hcur[(size_t)d * Bn * Hn + rem] = hnew;
            if (h0seq)
                h0seq[(size_t)d * SB * Hn + ((size_t)t * Bn + b) * Hn + j] = hnew;
            if (out) {
                out[((size_t)b * Sn + t) * (2 * Hn) + (size_t)d * Hn + j] = hnew;
                if (t == Sn - 1)
                    out[(size_t)Bn * Sn * 2 * Hn + (size_t)b * 2 * Hn + (size_t)d * Hn + j] = hnew;
            }
        }

        grid_barrier();
    }
}

// ----------------------------------------------------------------------------
// Launcher
// ----------------------------------------------------------------------------
extern "C" void kernel_launch(void* const* d_in, const int* in_sizes, int n_in,
                              void* d_out, int out_size) {
    const float* x      = (const float*)d_in[0];
    const float* w_ih0f = (const float*)d_in[1];
    const float* w_hh0f = (const float*)d_in[2];
    const float* b_ih0f = (const float*)d_in[3];
    const float* b_hh0f = (const float*)d_in[4];
    const float* w_ih0b = (const float*)d_in[5];
    const float* w_hh0b = (const float*)d_in[6];
    const float* b_ih0b = (const float*)d_in[7];
    const float* b_hh0b = (const float*)d_in[8];
    const float* w_ih1f = (const float*)d_in[9];
    const float* w_hh1f = (const float*)d_in[10];
    const float* b_ih1f = (const float*)d_in[11];
    const float* b_hh1f = (const float*)d_in[12];
    const float* w_ih1b = (const float*)d_in[13];
    const float* w_hh1b = (const float*)d_in[14];
    const float* b_ih1b = (const float*)d_in[15];
    const float* b_hh1b = (const float*)d_in[16];
    float* out = (float*)d_out;

    float *xT, *gi, *h0seq, *gh, *hcur, *bias0, *bias1;
    __nv_bfloat16 *wih0h, *wih0l, *whh0h, *whh0l, *wih1h, *wih1l, *whh1h, *whh1l;
    cudaGetSymbolAddress((void**)&xT,    g_xT);
    cudaGetSymbolAddress((void**)&gi,    g_gi);
    cudaGetSymbolAddress((void**)&h0seq, g_h0seq);
    cudaGetSymbolAddress((void**)&gh,    g_gh);
    cudaGetSymbolAddress((void**)&hcur,  g_hcur);
    cudaGetSymbolAddress((void**)&bias0, g_bias0);
    cudaGetSymbolAddress((void**)&bias1, g_bias1);
    cudaGetSymbolAddress((void**)&wih0h, g_wih0_hi);
    cudaGetSymbolAddress((void**)&wih0l, g_wih0_lo);
    cudaGetSymbolAddress((void**)&whh0h, g_whh0_hi);
    cudaGetSymbolAddress((void**)&whh0l, g_whh0_lo);
    cudaGetSymbolAddress((void**)&wih1h, g_wih1_hi);
    cudaGetSymbolAddress((void**)&wih1l, g_wih1_lo);
    cudaGetSymbolAddress((void**)&whh1h, g_whh1_hi);
    cudaGetSymbolAddress((void**)&whh1l, g_whh1_lo);

    // ---- prep ----
    k_xT<<<4096, 256>>>(x, xT);
    k_split<<<2048, 256>>>(w_ih0f, wih0h, wih0l, G3 * INn);
    k_split_rev<<<2048, 256>>>(w_ih0b, wih0h + (size_t)G3 * INn,
                               wih0l + (size_t)G3 * INn, G3, INn);
    k_split<<<2048, 256>>>(w_hh0f, whh0h, whh0l, G3 * Hn);
    k_split<<<2048, 256>>>(w_hh0b, whh0h + (size_t)G3 * Hn,
                           whh0l + (size_t)G3 * Hn, G3 * Hn);
    k_split<<<2048, 256>>>(w_ih1f, wih1h, wih1l, G3 * Hn);
    k_split<<<2048, 256>>>(w_ih1b, wih1h + (size_t)G3 * Hn,
                           wih1l + (size_t)G3 * Hn, G3 * Hn);
    k_split<<<2048, 256>>>(w_hh1f, whh1h, whh1l, G3 * Hn);
    k_split<<<2048, 256>>>(w_hh1b, whh1h + (size_t)G3 * Hn,
                           whh1l + (size_t)G3 * Hn, G3 * Hn);
    k_bias<<<12, 256>>>(b_ih0f, b_hh0f, bias0);
    k_bias<<<12, 256>>>(b_ih0b, b_hh0b, bias0 + G3);
    k_bias<<<12, 256>>>(b_ih1f, b_hh1f, bias1);
    k_bias<<<12, 256>>>(b_ih1b, b_hh1b, bias1 + G3);

    // ---- layer 0: batched input projection ----
    k_gemm<<<dim3(G3 / 64, SB / 64, 2), 256>>>(
        xT, 0, wih0h, wih0l, (size_t)G3 * INn,
        bias0, G3, gi, (size_t)SB * G3, G3, INn);

    // ---- layer 0 recurrence (single persistent kernel) ----
    k_recur<<<NBLK, 256>>>(whh0h, whh0l, gi, gh, hcur,
                           b_hh0f, b_hh0b, h0seq, nullptr);

    // ---- layer 1: batched input projection ----
    k_gemm<<<dim3(G3 / 64, SB / 64, 2), 256>>>(
        h0seq, (size_t)SB * Hn, wih1h, wih1l, (size_t)G3 * Hn,
        bias1, G3, gi, (size_t)SB * G3, G3, Hn);

    // ---- layer 1 recurrence ----
    k_recur<<<NBLK, 256>>>(whh1h, whh1l, gi, gh, hcur,
                           b_hh1f, b_hh1b, nullptr, out);
}

// round 4
// speedup vs baseline: 1.5201x; 1.5201x over previous
#include <cuda_runtime.h>
#include <cuda_bf16.h>
#include <stdint.h>
#include <math.h>

// Problem constants
#define Bn  64
#define Sn  512
#define INn 512
#define Hn  1024
#define G3  3072          // 3*H
#define SB  32768         // S*B

#define NRBLK 128         // persistent recurrence grid (2 dirs x 64 tiles of 48 rows)
#define RB    48          // W rows per recurrence block
#define SWPAD 1032        // W smem row stride (bf16 elems): 1024 + 8 -> conflict-free

// ----------------------------------------------------------------------------
// Device scratch (static — no allocations allowed)
// ----------------------------------------------------------------------------
__device__ __nv_bfloat16 g_x_hi[(size_t)SB * INn];    // split x, [s*B+b][IN]
__device__ __nv_bfloat16 g_x_lo[(size_t)SB * INn];
__device__ float g_gi[(size_t)2 * SB * G3];           // input-side gates per dir
__device__ __nv_bfloat16 g_h0_hi[(size_t)2 * SB * Hn];// layer-0 hidden seq (split)
__device__ __nv_bfloat16 g_h0_lo[(size_t)2 * SB * Hn];
__device__ float g_gh[2 * Bn * G3];                   // per-step hidden gates
__device__ float g_hcur[2 * Bn * Hn];                 // fp32 hidden state
__device__ __nv_bfloat16 g_hA_hi[2 * Bn * Hn];        // split hidden state (GEMM A)
__device__ __nv_bfloat16 g_hA_lo[2 * Bn * Hn];
__device__ float g_bias0[2 * G3];
__device__ float g_bias1[2 * G3];

__device__ __nv_bfloat16 g_wih0_hi[(size_t)2 * G3 * INn];
__device__ __nv_bfloat16 g_wih0_lo[(size_t)2 * G3 * INn];
__device__ __nv_bfloat16 g_whh0_hi[(size_t)2 * G3 * Hn];
__device__ __nv_bfloat16 g_whh0_lo[(size_t)2 * G3 * Hn];
__device__ __nv_bfloat16 g_wih1_hi[(size_t)2 * G3 * Hn];
__device__ __nv_bfloat16 g_wih1_lo[(size_t)2 * G3 * Hn];
__device__ __nv_bfloat16 g_whh1_hi[(size_t)2 * G3 * Hn];
__device__ __nv_bfloat16 g_whh1_lo[(size_t)2 * G3 * Hn];

// grid barrier state
__device__ volatile unsigned g_bar_gen;
__device__ unsigned g_bar_cnt;

// ----------------------------------------------------------------------------
// cp.async helpers
// ----------------------------------------------------------------------------
__device__ __forceinline__ void cp16(void* dst, const void* src) {
    uint32_t d = (uint32_t)__cvta_generic_to_shared(dst);
    asm volatile("cp.async.cg.shared.global [%0], [%1], 16;\n" :: "r"(d), "l"(src));
}
#define CP_COMMIT() asm volatile("cp.async.commit_group;\n")
#define CP_WAIT0()  asm volatile("cp.async.wait_group 0;\n")

// ----------------------------------------------------------------------------
// Prep kernels
// ----------------------------------------------------------------------------
__global__ void k_xT_split(const float* __restrict__ x,
                           __nv_bfloat16* __restrict__ hi,
                           __nv_bfloat16* __restrict__ lo) {
    size_t total = (size_t)Bn * Sn * INn;
    for (size_t i = (size_t)blockIdx.x * blockDim.x + threadIdx.x; i < total;
         i += (size_t)gridDim.x * blockDim.x) {
        int k = (int)(i % INn);
        size_t tmp = i / INn;
        int s = (int)(tmp % Sn);
        int b = (int)(tmp / Sn);
        float v = x[i];
        __nv_bfloat16 h = __float2bfloat16(v);
        size_t o = ((size_t)s * Bn + b) * INn + k;
        hi[o] = h;
        lo[o] = __float2bfloat16(v - __bfloat162float(h));
    }
}

__global__ void k_split(const float* __restrict__ src, __nv_bfloat16* __restrict__ hi,
                        __nv_bfloat16* __restrict__ lo, int n) {
    for (int i = blockIdx.x * blockDim.x + threadIdx.x; i < n;
         i += gridDim.x * blockDim.x) {
        float v = src[i];
        __nv_bfloat16 h = __float2bfloat16(v);
        hi[i] = h;
        lo[i] = __float2bfloat16(v - __bfloat162float(h));
    }
}

__global__ void k_split_rev(const float* __restrict__ src, __nv_bfloat16* __restrict__ hi,
                            __nv_bfloat16* __restrict__ lo, int N, int K) {
    int total = N * K;
    for (int i = blockIdx.x * blockDim.x + threadIdx.x; i < total;
         i += gridDim.x * blockDim.x) {
        int n = i / K;
        int k = i % K;
        float v = src[(size_t)n * K + (K - 1 - k)];
        __nv_bfloat16 h = __float2bfloat16(v);
        hi[i] = h;
        lo[i] = __float2bfloat16(v - __bfloat162float(h));
    }
}

__global__ void k_bias(const float* __restrict__ bih, const float* __restrict__ bhh,
                       float* __restrict__ dst) {
    int n = blockIdx.x * blockDim.x + threadIdx.x;
    if (n < G3) dst[n] = bih[n] + (n < 2 * Hn ? bhh[n] : 0.0f);
}

// ----------------------------------------------------------------------------
// MMA helper
// ----------------------------------------------------------------------------
__device__ __forceinline__ void mma_bf16(float c[4], const uint32_t a[4],
                                         uint32_t b0, uint32_t b1) {
    asm("mma.sync.aligned.m16n8k16.row.col.f32.bf16.bf16.f32 "
        "{%0,%1,%2,%3}, {%4,%5,%6,%7}, {%8,%9}, {%0,%1,%2,%3};\n"
        : "+f"(c[0]), "+f"(c[1]), "+f"(c[2]), "+f"(c[3])
        : "r"(a[0]), "r"(a[1]), "r"(a[2]), "r"(a[3]), "r"(b0), "r"(b1));
}

// ----------------------------------------------------------------------------
// Batched split-bf16 GEMM with cp.async double buffering.
// C[M,N] = A[M,K] * W[N,K]^T (+bias). A pre-split bf16 hi/lo.
// Block tile 64x64, BK=32, 8 warps (4 M x 2 N).
// ----------------------------------------------------------------------------
__global__ __launch_bounds__(256) void k_gemm(
    const __nv_bfloat16* __restrict__ Ahi, const __nv_bfloat16* __restrict__ Alo,
    size_t aStrZ,
    const __nv_bfloat16* __restrict__ Whi, const __nv_bfloat16* __restrict__ Wlo,
    size_t wStrZ,
    const float* __restrict__ bias, size_t bStrZ,
    float* __restrict__ C, size_t cStrZ,
    int N, int K)
{
    const int z = blockIdx.z;
    Ahi += (size_t)z * aStrZ;
    Alo += (size_t)z * aStrZ;
    Whi += (size_t)z * wStrZ;
    Wlo += (size_t)z * wStrZ;
    const float* biasz = bias ? (bias + (size_t)z * bStrZ) : nullptr;
    C   += (size_t)z * cStrZ;

    const int m0 = blockIdx.y * 64;
    const int n0 = blockIdx.x * 64;

    __shared__ __align__(16) __nv_bfloat16 sA[2][2][64][40];  // [buf][hi/lo][m][k]
    __shared__ __align__(16) __nv_bfloat16 sW[2][2][64][40];

    const int tid  = threadIdx.x;
    const int lane = tid & 31;
    const int warp = tid >> 5;
    const int wm = warp & 3;
    const int wn = warp >> 2;
    const int g  = lane >> 2;
    const int tq = lane & 3;
    const int crow = tid >> 2;   // copy row 0..63
    const int cq   = tid & 3;    // copy chunk 0..3 (8 bf16 each)

    float acc[4][4];
#pragma unroll
    for (int i = 0; i < 4; i++)
#pragma unroll
        for (int j = 0; j < 4; j++) acc[i][j] = 0.0f;

    // prologue copy (buf 0, k0 = 0)
    {
        const size_t ao = (size_t)(m0 + crow) * K + cq * 8;
        const size_t wo = (size_t)(n0 + crow) * K + cq * 8;
        cp16(&sA[0][0][crow][cq * 8], Ahi + ao);
        cp16(&sA[0][1][crow][cq * 8], Alo + ao);
        cp16(&sW[0][0][crow][cq * 8], Whi + wo);
        cp16(&sW[0][1][crow][cq * 8], Wlo + wo);
        CP_COMMIT();
    }

    int buf = 0;
    for (int k0 = 0; k0 < K; k0 += 32, buf ^= 1) {
        CP_WAIT0();
        __syncthreads();
        if (k0 + 32 < K) {
            const size_t ao = (size_t)(m0 + crow) * K + (k0 + 32) + cq * 8;
            const size_t wo = (size_t)(n0 + crow) * K + (k0 + 32) + cq * 8;
            cp16(&sA[buf ^ 1][0][crow][cq * 8], Ahi + ao);
            cp16(&sA[buf ^ 1][1][crow][cq * 8], Alo + ao);
            cp16(&sW[buf ^ 1][0][crow][cq * 8], Whi + wo);
            cp16(&sW[buf ^ 1][1][crow][cq * 8], Wlo + wo);
            CP_COMMIT();
        }

#pragma unroll
        for (int kk = 0; kk < 32; kk += 16) {
            const int ar = wm * 16 + g;
            const int ac = kk + tq * 2;
            uint32_t ah[4], al[4];
            ah[0] = *reinterpret_cast<const uint32_t*>(&sA[buf][0][ar    ][ac    ]);
            ah[1] = *reinterpret_cast<const uint32_t*>(&sA[buf][0][ar + 8][ac    ]);
            ah[2] = *reinterpret_cast<const uint32_t*>(&sA[buf][0][ar    ][ac + 8]);
            ah[3] = *reinterpret_cast<const uint32_t*>(&sA[buf][0][ar + 8][ac + 8]);
            al[0] = *reinterpret_cast<const uint32_t*>(&sA[buf][1][ar    ][ac    ]);
            al[1] = *reinterpret_cast<const uint32_t*>(&sA[buf][1][ar + 8][ac    ]);
            al[2] = *reinterpret_cast<const uint32_t*>(&sA[buf][1][ar    ][ac + 8]);
            al[3] = *reinterpret_cast<const uint32_t*>(&sA[buf][1][ar + 8][ac + 8]);
#pragma unroll
            for (int nf = 0; nf < 4; nf++) {
                const int br = wn * 32 + nf * 8 + g;
                uint32_t bh0 = *reinterpret_cast<const uint32_t*>(&sW[buf][0][br][ac    ]);
                uint32_t bh1 = *reinterpret_cast<const uint32_t*>(&sW[buf][0][br][ac + 8]);
                uint32_t bl0 = *reinterpret_cast<const uint32_t*>(&sW[buf][1][br][ac    ]);
                uint32_t bl1 = *reinterpret_cast<const uint32_t*>(&sW[buf][1][br][ac + 8]);
                mma_bf16(acc[nf], ah, bh0, bh1);
                mma_bf16(acc[nf], ah, bl0, bl1);
                mma_bf16(acc[nf], al, bh0, bh1);
            }
        }
    }

#pragma unroll
    for (int nf = 0; nf < 4; nf++) {
        int col = n0 + wn * 32 + nf * 8 + tq * 2;
        float b0 = biasz ? biasz[col]     : 0.0f;
        float b1 = biasz ? biasz[col + 1] : 0.0f;
        int row = m0 + wm * 16 + g;
        float* c0 = C + (size_t)row * N + col;
        c0[0] = acc[nf][0] + b0;
        c0[1] = acc[nf][1] + b1;
        float* c1 = C + (size_t)(row + 8) * N + col;
        c1[0] = acc[nf][2] + b0;
        c1[1] = acc[nf][3] + b1;
    }
}

// ----------------------------------------------------------------------------
// Software grid barrier (all NRBLK blocks co-resident)
// ----------------------------------------------------------------------------
__device__ __forceinline__ void grid_barrier() {
    __syncthreads();
    if (threadIdx.x == 0) {
        unsigned gen = g_bar_gen;
        __threadfence();
        if (atomicAdd(&g_bar_cnt, 1) == NRBLK - 1) {
            g_bar_cnt = 0;
            __threadfence();
            g_bar_gen = gen + 1;
        } else {
            while (g_bar_gen == gen) { __nanosleep(64); }
        }
        __threadfence();
    }
    __syncthreads();
}

// ----------------------------------------------------------------------------
// Persistent recurrence kernel with weight-resident smem.
// Grid: 128 blocks = 2 dirs x 64 tiles (48 W-rows each), 256 threads.
// Dynamic smem: W hi/lo [48][1032] (198 KB) + A double buffer (20 KB).
// ----------------------------------------------------------------------------
__global__ __launch_bounds__(256) void k_recur(
    const __nv_bfloat16* __restrict__ Whi,  // [2][G3][Hn]
    const __nv_bfloat16* __restrict__ Wlo,
    const float* __restrict__ gi,           // [2][SB][G3]
    float* __restrict__ gh,                 // [2][B][G3]
    float* __restrict__ hcur,               // [2][B][H] fp32
    __nv_bfloat16* __restrict__ hAhi,       // [2][B][H] split
    __nv_bfloat16* __restrict__ hAlo,
    const float* __restrict__ bhh_f, const float* __restrict__ bhh_b,
    __nv_bfloat16* __restrict__ h0hi,       // [2][SB][H] or null
    __nv_bfloat16* __restrict__ h0lo,
    float* __restrict__ out)                // or null
{
    extern __shared__ __align__(16) char sm_raw[];
    __nv_bfloat16* sWhi = reinterpret_cast<__nv_bfloat16*>(sm_raw);      // [RB][SWPAD]
    __nv_bfloat16* sWlo = sWhi + RB * SWPAD;
    __nv_bfloat16* sAb  = sWlo + RB * SWPAD;  // [2][2][64][40]

    const int tid  = threadIdx.x;
    const int dir  = blockIdx.x >> 6;         // 0..1
    const int n0   = (blockIdx.x & 63) * RB;  // W row offset within dir

    const __nv_bfloat16* WhiD = Whi + (size_t)dir * G3 * Hn;
    const __nv_bfloat16* WloD = Wlo + (size_t)dir * G3 * Hn;
    const __nv_bfloat16* AhiD = hAhi + (size_t)dir * Bn * Hn;
    const __nv_bfloat16* AloD = hAlo + (size_t)dir * Bn * Hn;
    float* ghD = gh + (size_t)dir * Bn * G3;

    const int lane = tid & 31;
    const int warp = tid >> 5;
    const int wm = warp & 3;        // M tile (16 rows)
    const int wn = warp >> 2;       // 0..1 -> 24 cols
    const int g  = lane >> 2;
    const int tq = lane & 3;
    const int crow = tid >> 2;      // A copy row 0..63
    const int cq   = tid & 3;

    // ---- load resident W slice (once) ----
    for (int i = tid; i < RB * (Hn / 8); i += 256) {
        int row = i >> 7;           // Hn/8 = 128 chunks per row
        int q   = i & 127;
        const size_t off = (size_t)(n0 + row) * Hn + q * 8;
        cp16(&sWhi[row * SWPAD + q * 8], WhiD + off);
        cp16(&sWlo[row * SWPAD + q * 8], WloD + off);
    }
    CP_COMMIT();

    // ---- zero state ----
    for (int i = blockIdx.x * 256 + tid; i < 2 * Bn * Hn; i += NRBLK * 256) {
        hcur[i] = 0.0f;
        hAhi[i] = __float2bfloat16(0.0f);
        hAlo[i] = __float2bfloat16(0.0f);
    }
    CP_WAIT0();
    grid_barrier();

    #define SA(b, c, r, k) sAb[(((b) * 2 + (c)) * 64 + (r)) * 40 + (k)]

    for (int t = 0; t < Sn; ++t) {
        // ---- GEMM: gh[n0:n0+48] = hcur (64x1024) x W_slice^T ----
        float acc[3][4];
#pragma unroll
        for (int i = 0; i < 3; i++)
#pragma unroll
            for (int j = 0; j < 4; j++) acc[i][j] = 0.0f;

        // prologue A copy (buf 0, k0 = 0)
        {
            const size_t ao = (size_t)crow * Hn + cq * 8;
            cp16(&SA(0, 0, crow, cq * 8), AhiD + ao);
            cp16(&SA(0, 1, crow, cq * 8), AloD + ao);
            CP_COMMIT();
        }

        int buf = 0;
        for (int k0 = 0; k0 < Hn; k0 += 32, buf ^= 1) {
            CP_WAIT0();
            __syncthreads();
            if (k0 + 32 < Hn) {
                const size_t ao = (size_t)crow * Hn + (k0 + 32) + cq * 8;
                cp16(&SA(buf ^ 1, 0, crow, cq * 8), AhiD + ao);
                cp16(&SA(buf ^ 1, 1, crow, cq * 8), AloD + ao);
                CP_COMMIT();
            }

#pragma unroll
            for (int kk = 0; kk < 32; kk += 16) {
                const int ar = wm * 16 + g;
                const int ac = kk + tq * 2;
                uint32_t ah[4], al[4];
                ah[0] = *reinterpret_cast<const uint32_t*>(&SA(buf, 0, ar,     ac    ));
                ah[1] = *reinterpret_cast<const uint32_t*>(&SA(buf, 0, ar + 8, ac    ));
                ah[2] = *reinterpret_cast<const uint32_t*>(&SA(buf, 0, ar,     ac + 8));
                ah[3] = *reinterpret_cast<const uint32_t*>(&SA(buf, 0, ar + 8, ac + 8));
                al[0] = *reinterpret_cast<const uint32_t*>(&SA(buf, 1, ar,     ac    ));
                al[1] = *reinterpret_cast<const uint32_t*>(&SA(buf, 1, ar + 8, ac    ));
                al[2] = *reinterpret_cast<const uint32_t*>(&SA(buf, 1, ar,     ac + 8));
                al[3] = *reinterpret_cast<const uint32_t*>(&SA(buf, 1, ar + 8, ac + 8));
                const int col = k0 + kk + tq * 2;
#pragma unroll
                for (int nf = 0; nf < 3; nf++) {
                    const int br = wn * 24 + nf * 8 + g;
                    uint32_t bh0 = *reinterpret_cast<const uint32_t*>(&sWhi[br * SWPAD + col    ]);
                    uint32_t bh1 = *reinterpret_cast<const uint32_t*>(&sWhi[br * SWPAD + col + 8]);
                    uint32_t bl0 = *reinterpret_cast<const uint32_t*>(&sWlo[br * SWPAD + col    ]);
                    uint32_t bl1 = *reinterpret_cast<const uint32_t*>(&sWlo[br * SWPAD + col + 8]);
                    mma_bf16(acc[nf], ah, bh0, bh1);
                    mma_bf16(acc[nf], ah, bl0, bl1);
                    mma_bf16(acc[nf], al, bh0, bh1);
                }
            }
        }

        // write gh tile
#pragma unroll
        for (int nf = 0; nf < 3; nf++) {
            int col = n0 + wn * 24 + nf * 8 + tq * 2;
            int row = wm * 16 + g;
            float* c0 = ghD + (size_t)row * G3 + col;
            c0[0] = acc[nf][0];
            c0[1] = acc[nf][1];
            float* c1 = ghD + (size_t)(row + 8) * G3 + col;
            c1[0] = acc[nf][2];
            c1[1] = acc[nf][3];
        }

        grid_barrier();

        // ---- gate phase ----
        for (int idx = blockIdx.x * 256 + tid; idx < 2 * Bn * Hn; idx += NRBLK * 256) {
            int d   = idx >> 16;            // Bn*Hn = 65536
            int rem = idx & 65535;
            int b   = rem >> 10;
            int j   = rem & (Hn - 1);

            const float* giD = gi + (size_t)d * SB * G3 + ((size_t)t * Bn + b) * G3;
            const float* ghd = gh + (size_t)d * Bn * G3 + (size_t)b * G3;
            const float* bhh = d ? bhh_b : bhh_f;

            float ir  = giD[j];
            float iz  = giD[Hn + j];
            float inn = giD[2 * Hn + j];
            float hr  = ghd[j];
            float hz  = ghd[Hn + j];
            float hn  = ghd[2 * Hn + j] + bhh[2 * Hn + j];
            float h   = hcur[idx];

            float r  = 1.0f / (1.0f + expf(-(ir + hr)));
            float zz = 1.0f / (1.0f + expf(-(iz + hz)));
            float n  = tanhf(inn + r * hn);
            float hnew = (1.0f - zz) * n + zz * h;

            hcur[idx] = hnew;
            __nv_bfloat16 hi = __float2bfloat16(hnew);
            __nv_bfloat16 lo = __float2bfloat16(hnew - __bfloat162float(hi));
            hAhi[idx] = hi;
            hAlo[idx] = lo;
            if (h0hi) {
                size_t o = (size_t)d * SB * Hn + ((size_t)t * Bn + b) * Hn + j;
                h0hi[o] = hi;
                h0lo[o] = lo;
            }
            if (out) {
                out[((size_t)b * Sn + t) * (2 * Hn) + (size_t)d * Hn + j] = hnew;
                if (t == Sn - 1)
                    out[(size_t)Bn * Sn * 2 * Hn + (size_t)b * 2 * Hn + (size_t)d * Hn + j] = hnew;
            }
        }

        grid_barrier();
    }
    #undef SA
}

// ----------------------------------------------------------------------------
// Launcher
// ----------------------------------------------------------------------------
extern "C" void kernel_launch(void* const* d_in, const int* in_sizes, int n_in,
                              void* d_out, int out_size) {
    const float* x      = (const float*)d_in[0];
    const float* w_ih0f = (const float*)d_in[1];
    const float* w_hh0f = (const float*)d_in[2];
    const float* b_ih0f = (const float*)d_in[3];
    const float* b_hh0f = (const float*)d_in[4];
    const float* w_ih0b = (const float*)d_in[5];
    const float* w_hh0b = (const float*)d_in[6];
    const float* b_ih0b = (const float*)d_in[7];
    const float* b_hh0b = (const float*)d_in[8];
    const float* w_ih1f = (const float*)d_in[9];
    const float* w_hh1f = (const float*)d_in[10];
    const float* b_ih1f = (const float*)d_in[11];
    const float* b_hh1f = (const float*)d_in[12];
    const float* w_ih1b = (const float*)d_in[13];
    const float* w_hh1b = (const float*)d_in[14];
    const float* b_ih1b = (const float*)d_in[15];
    const float* b_hh1b = (const float*)d_in[16];
    float* out = (float*)d_out;

    float *gi, *gh, *hcur, *bias0, *bias1;
    __nv_bfloat16 *xhi, *xlo, *h0hi, *h0lo, *hAhi, *hAlo;
    __nv_bfloat16 *wih0h, *wih0l, *whh0h, *whh0l, *wih1h, *wih1l, *whh1h, *whh1l;
    cudaGetSymbolAddress((void**)&xhi,   g_x_hi);
    cudaGetSymbolAddress((void**)&xlo,   g_x_lo);
    cudaGetSymbolAddress((void**)&gi,    g_gi);
    cudaGetSymbolAddress((void**)&h0hi,  g_h0_hi);
    cudaGetSymbolAddress((void**)&h0lo,  g_h0_lo);
    cudaGetSymbolAddress((void**)&gh,    g_gh);
    cudaGetSymbolAddress((void**)&hcur,  g_hcur);
    cudaGetSymbolAddress((void**)&hAhi,  g_hA_hi);
    cudaGetSymbolAddress((void**)&hAlo,  g_hA_lo);
    cudaGetSymbolAddress((void**)&bias0, g_bias0);
    cudaGetSymbolAddress((void**)&bias1, g_bias1);
    cudaGetSymbolAddress((void**)&wih0h, g_wih0_hi);
    cudaGetSymbolAddress((void**)&wih0l, g_wih0_lo);
    cudaGetSymbolAddress((void**)&whh0h, g_whh0_hi);
    cudaGetSymbolAddress((void**)&whh0l, g_whh0_lo);
    cudaGetSymbolAddress((void**)&wih1h, g_wih1_hi);
    cudaGetSymbolAddress((void**)&wih1l, g_wih1_lo);
    cudaGetSymbolAddress((void**)&whh1h, g_whh1_hi);
    cudaGetSymbolAddress((void**)&whh1l, g_whh1_lo);

    const int SMEM_RECUR = (2 * RB * SWPAD + 2 * 2 * 64 * 40) * (int)sizeof(__nv_bfloat16);
    static bool attr_done = false;
    if (!attr_done) {
        cudaFuncSetAttribute(k_recur, cudaFuncAttributeMaxDynamicSharedMemorySize,
                             SMEM_RECUR);
        attr_done = true;
    }

    // ---- prep ----
    k_xT_split<<<2048, 256>>>(x, xhi, xlo);
    k_split<<<2048, 256>>>(w_ih0f, wih0h, wih0l, G3 * INn);
    k_split_rev<<<2048, 256>>>(w_ih0b, wih0h + (size_t)G3 * INn,
                               wih0l + (size_t)G3 * INn, G3, INn);
    k_split<<<2048, 256>>>(w_hh0f, whh0h, whh0l, G3 * Hn);
    k_split<<<2048, 256>>>(w_hh0b, whh0h + (size_t)G3 * Hn,
                           whh0l + (size_t)G3 * Hn, G3 * Hn);
    k_split<<<2048, 256>>>(w_ih1f, wih1h, wih1l, G3 * Hn);
    k_split<<<2048, 256>>>(w_ih1b, wih1h + (size_t)G3 * Hn,
                           wih1l + (size_t)G3 * Hn, G3 * Hn);
    k_split<<<2048, 256>>>(w_hh1f, whh1h, whh1l, G3 * Hn);
    k_split<<<2048, 256>>>(w_hh1b, whh1h + (size_t)G3 * Hn,
                           whh1l + (size_t)G3 * Hn, G3 * Hn);
    k_bias<<<12, 256>>>(b_ih0f, b_hh0f, bias0);
    k_bias<<<12, 256>>>(b_ih0b, b_hh0b, bias0 + G3);
    k_bias<<<12, 256>>>(b_ih1f, b_hh1f, bias1);
    k_bias<<<12, 256>>>(b_ih1b, b_hh1b, bias1 + G3);

    // ---- layer 0: batched input projection (x shared across dirs) ----
    k_gemm<<<dim3(G3 / 64, SB / 64, 2), 256>>>(
        xhi, xlo, 0,
        wih0h, wih0l, (size_t)G3 * INn,
        bias0, G3, gi, (size_t)SB * G3, G3, INn);

    // ---- layer 0 recurrence ----
    k_recur<<<NRBLK, 256, SMEM_RECUR>>>(
        whh0h, whh0l, gi, gh, hcur, hAhi, hAlo,
        b_hh0f, b_hh0b, h0hi, h0lo, nullptr);

    // ---- layer 1: batched input projection (per-dir A) ----
    k_gemm<<<dim3(G3 / 64, SB / 64, 2), 256>>>(
        h0hi, h0lo, (size_t)SB * Hn,
        wih1h, wih1l, (size_t)G3 * Hn,
        bias1, G3, gi, (size_t)SB * G3, G3, Hn);

    // ---- layer 1 recurrence (writes output) ----
    k_recur<<<NRBLK, 256, SMEM_RECUR>>>(
        whh1h, whh1l, gi, gh, hcur, hAhi, hAlo,
        b_hh1f, b_hh1b, nullptr, nullptr, out);
}

// round 5
// speedup vs baseline: 1.7303x; 1.1383x over previous
#include <cuda_runtime.h>
#include <cuda_bf16.h>
#include <stdint.h>
#include <math.h>

// Problem constants
#define Bn  64
#define Sn  512
#define INn 512
#define Hn  1024
#define G3  3072          // 3*H
#define SB  32768         // S*B

#define NRBLK 128         // recurrence grid: 2 dirs x 64 tiles (16 j-cols, 48 W rows)
#define RB    48
#define SWPAD 1032        // resident W smem row stride (bf16 elems)

// ----------------------------------------------------------------------------
// Device scratch (static — no allocations allowed)
// ----------------------------------------------------------------------------
__device__ __nv_bfloat16 g_x_hi[(size_t)SB * INn];
__device__ __nv_bfloat16 g_x_lo[(size_t)SB * INn];
__device__ float g_gi[(size_t)2 * SB * G3];
__device__ __nv_bfloat16 g_h0_hi[(size_t)2 * SB * Hn];
__device__ __nv_bfloat16 g_h0_lo[(size_t)2 * SB * Hn];
__device__ float g_hcur[2 * Bn * Hn];
__device__ __nv_bfloat16 g_hA_hi[2 * Bn * Hn];
__device__ __nv_bfloat16 g_hA_lo[2 * Bn * Hn];
__device__ float g_bias0[2 * G3];
__device__ float g_bias1[2 * G3];

__device__ __nv_bfloat16 g_wih0_hi[(size_t)2 * G3 * INn];
__device__ __nv_bfloat16 g_wih0_lo[(size_t)2 * G3 * INn];
__device__ __nv_bfloat16 g_wih1_hi[(size_t)2 * G3 * Hn];
__device__ __nv_bfloat16 g_wih1_lo[(size_t)2 * G3 * Hn];
// W_hh stored ROW-PERMUTED: row p = tile*48 + gate*16 + jj  <-  src row gate*H + tile*16 + jj
__device__ __nv_bfloat16 g_whh0_hi[(size_t)2 * G3 * Hn];
__device__ __nv_bfloat16 g_whh0_lo[(size_t)2 * G3 * Hn];
__device__ __nv_bfloat16 g_whh1_hi[(size_t)2 * G3 * Hn];
__device__ __nv_bfloat16 g_whh1_lo[(size_t)2 * G3 * Hn];

__device__ volatile unsigned g_bar_gen;
__device__ unsigned g_bar_cnt;

// ----------------------------------------------------------------------------
// cp.async / ldmatrix helpers
// ----------------------------------------------------------------------------
__device__ __forceinline__ void cp16(void* dst, const void* src) {
    uint32_t d = (uint32_t)__cvta_generic_to_shared(dst);
    asm volatile("cp.async.cg.shared.global [%0], [%1], 16;\n" :: "r"(d), "l"(src));
}
#define CP_COMMIT() asm volatile("cp.async.commit_group;\n")
#define CP_WAIT0()  asm volatile("cp.async.wait_group 0;\n")
#define CP_WAIT1()  asm volatile("cp.async.wait_group 1;\n")

__device__ __forceinline__ void ldsm4(uint32_t r[4], uint32_t saddr) {
    asm volatile("ldmatrix.sync.aligned.m8n8.x4.shared.b16 {%0,%1,%2,%3}, [%4];"
                 : "=r"(r[0]), "=r"(r[1]), "=r"(r[2]), "=r"(r[3]) : "r"(saddr));
}
__device__ __forceinline__ void ldsm2(uint32_t r[2], uint32_t saddr) {
    asm volatile("ldmatrix.sync.aligned.m8n8.x2.shared.b16 {%0,%1}, [%2];"
                 : "=r"(r[0]), "=r"(r[1]) : "r"(saddr));
}

__device__ __forceinline__ void mma_bf16(float c[4], const uint32_t a[4],
                                         uint32_t b0, uint32_t b1) {
    asm("mma.sync.aligned.m16n8k16.row.col.f32.bf16.bf16.f32 "
        "{%0,%1,%2,%3}, {%4,%5,%6,%7}, {%8,%9}, {%0,%1,%2,%3};\n"
        : "+f"(c[0]), "+f"(c[1]), "+f"(c[2]), "+f"(c[3])
        : "r"(a[0]), "r"(a[1]), "r"(a[2]), "r"(a[3]), "r"(b0), "r"(b1));
}

// ----------------------------------------------------------------------------
// Prep: all weight splits (+ W_hh permutation) + biases, one kernel
// ----------------------------------------------------------------------------
__device__ __forceinline__ void split_at(const float* src, size_t si,
                                         __nv_bfloat16* hi, __nv_bfloat16* lo, size_t di) {
    float v = src[si];
    __nv_bfloat16 h = __float2bfloat16(v);
    hi[di] = h;
    lo[di] = __float2bfloat16(v - __bfloat162float(h));
}

__global__ void k_prep(
    const float* __restrict__ wih0f, const float* __restrict__ wih0b,
    const float* __restrict__ wih1f, const float* __restrict__ wih1b,
    const float* __restrict__ whh0f, const float* __restrict__ whh0b,
    const float* __restrict__ whh1f, const float* __restrict__ whh1b,
    const float* __restrict__ bih0f, const float* __restrict__ bhh0f,
    const float* __restrict__ bih0b, const float* __restrict__ bhh0b,
    const float* __restrict__ bih1f, const float* __restrict__ bhh1f,
    const float* __restrict__ bih1b, const float* __restrict__ bhh1b)
{
    const int seg = blockIdx.y;
    const int stride = gridDim.x * blockDim.x;
    int i0 = blockIdx.x * blockDim.x + threadIdx.x;

    if (seg == 0) {           // wih0f plain
        for (int i = i0; i < G3 * INn; i += stride)
            split_at(wih0f, i, g_wih0_hi, g_wih0_lo, i);
    } else if (seg == 1) {    // wih0b feature-reversed
        for (int i = i0; i < G3 * INn; i += stride) {
            int n = i / INn, k = i % INn;
            split_at(wih0b, (size_t)n * INn + (INn - 1 - k),
                     g_wih0_hi, g_wih0_lo, (size_t)G3 * INn + i);
        }
    } else if (seg == 2) {    // wih1f plain
        for (int i = i0; i < G3 * Hn; i += stride)
            split_at(wih1f, i, g_wih1_hi, g_wih1_lo, i);
    } else if (seg == 3) {    // wih1b plain
        for (int i = i0; i < G3 * Hn; i += stride)
            split_at(wih1b, i, g_wih1_hi, g_wih1_lo, (size_t)G3 * Hn + i);
    } else if (seg <= 7) {    // whh: permuted rows
        const float* src = (seg == 4) ? whh0f : (seg == 5) ? whh0b
                         : (seg == 6) ? whh1f : whh1b;
        __nv_bfloat16* hi = (seg <= 5) ? g_whh0_hi : g_whh1_hi;
        __nv_bfloat16* lo = (seg <= 5) ? g_whh0_lo : g_whh1_lo;
        size_t doff = (seg == 5 || seg == 7) ? (size_t)G3 * Hn : 0;
        for (int i = i0; i < G3 * Hn; i += stride) {
            int prow = i >> 10, k = i & 1023;
            int tile = prow / 48, gate = (prow % 48) >> 4, jj = prow & 15;
            size_t srow = (size_t)gate * Hn + tile * 16 + jj;
            split_at(src, srow * Hn + k, hi, lo, doff + i);
        }
    } else {                  // biases: gi-side combined bias (b_ih + b_hh for r,z)
        for (int i = i0; i < G3; i += stride) {
            float add = (i < 2 * Hn) ? 1.0f : 0.0f;
            g_bias0[i]      = bih0f[i] + add * bhh0f[i];
            g_bias0[G3 + i] = bih0b[i] + add * bhh0b[i];
            g_bias1[i]      = bih1f[i] + add * bhh1f[i];
            g_bias1[G3 + i] = bih1b[i] + add * bhh1b[i];
        }
    }
}

__global__ void k_xT_split(const float* __restrict__ x,
                           __nv_bfloat16* __restrict__ hi,
                           __nv_bfloat16* __restrict__ lo) {
    size_t total = (size_t)Bn * Sn * INn;
    for (size_t i = (size_t)blockIdx.x * blockDim.x + threadIdx.x; i < total;
         i += (size_t)gridDim.x * blockDim.x) {
        int k = (int)(i % INn);
        size_t tmp = i / INn;
        int s = (int)(tmp % Sn);
        int b = (int)(tmp / Sn);
        float v = x[i];
        __nv_bfloat16 h = __float2bfloat16(v);
        size_t o = ((size_t)s * Bn + b) * INn + k;
        hi[o] = h;
        lo[o] = __float2bfloat16(v - __bfloat162float(h));
    }
}

// ----------------------------------------------------------------------------
// Batched split-bf16 GEMM, 128x64 tile, 3-stage cp.async, ldmatrix fragments.
// C[M,N] = A[M,K] * W[N,K]^T (+bias). 256 threads = 8 warps (4 M x 2 N).
// ----------------------------------------------------------------------------
__global__ __launch_bounds__(256) void k_gemm(
    const __nv_bfloat16* __restrict__ Ahi, const __nv_bfloat16* __restrict__ Alo,
    size_t aStrZ,
    const __nv_bfloat16* __restrict__ Whi, const __nv_bfloat16* __restrict__ Wlo,
    size_t wStrZ,
    const float* __restrict__ bias, size_t bStrZ,
    float* __restrict__ C, size_t cStrZ,
    int N, int K)
{
    const int z = blockIdx.z;
    Ahi += (size_t)z * aStrZ;  Alo += (size_t)z * aStrZ;
    Whi += (size_t)z * wStrZ;  Wlo += (size_t)z * wStrZ;
    const float* biasz = bias ? (bias + (size_t)z * bStrZ) : nullptr;
    C += (size_t)z * cStrZ;

    const int m0 = blockIdx.y * 128;
    const int n0 = blockIdx.x * 64;

    // smem: A [3][2][128][40], W [3][2][64][40]
    extern __shared__ __align__(16) __nv_bfloat16 sm[];
    __nv_bfloat16* sA = sm;                     // 3*2*128*40 = 30720 elems
    __nv_bfloat16* sW = sm + 3 * 2 * 128 * 40;  // 3*2*64*40  = 15360 elems
    const uint32_t sAaddr = (uint32_t)__cvta_generic_to_shared(sA);
    const uint32_t sWaddr = (uint32_t)__cvta_generic_to_shared(sW);

    const int tid  = threadIdx.x;
    const int lane = tid & 31;
    const int warp = tid >> 5;
    const int wm = warp & 3;      // 32 M rows per warp (2 subtiles of 16)
    const int wn = warp >> 2;     // 32 N cols per warp (4 nf of 8)
    const int g  = lane >> 2;
    const int tq = lane & 3;

    // copy mappings
    const int arow = tid >> 1;          // 0..127
    const int acol = (tid & 1) * 16;    // {0,16}
    const int wrow = tid >> 2;          // 0..63
    const int wcol = (tid & 3) * 8;

    // ldmatrix lane offsets
    const int lrow  = lane & 15;
    const int lcol8 = (lane >> 4) * 8;

    float acc[2][4][4];
#pragma unroll
    for (int a = 0; a < 2; a++)
#pragma unroll
        for (int b = 0; b < 4; b++)
#pragma unroll
            for (int c = 0; c < 4; c++) acc[a][b][c] = 0.0f;

    const int nk = K / 32;

    auto copy_chunk = [&](int ci, int st) {
        const int k0 = ci * 32;
        // A: 128x32 hi+lo
        const size_t ao = (size_t)(m0 + arow) * K + k0 + acol;
        __nv_bfloat16* dA0 = sA + ((st * 2 + 0) * 128 + arow) * 40 + acol;
        __nv_bfloat16* dA1 = sA + ((st * 2 + 1) * 128 + arow) * 40 + acol;
        cp16(dA0,     Ahi + ao);
        cp16(dA0 + 8, Ahi + ao + 8);
        cp16(dA1,     Alo + ao);
        cp16(dA1 + 8, Alo + ao + 8);
        // W: 64x32 hi+lo
        const size_t wo = (size_t)(n0 + wrow) * K + k0 + wcol;
        cp16(sW + ((st * 2 + 0) * 64 + wrow) * 40 + wcol, Whi + wo);
        cp16(sW + ((st * 2 + 1) * 64 + wrow) * 40 + wcol, Wlo + wo);
        CP_COMMIT();
    };

    copy_chunk(0, 0);
    copy_chunk(1, 1);

    for (int ci = 0; ci < nk; ci++) {
        const int st = ci % 3;
        CP_WAIT1();
        __syncthreads();
        if (ci + 2 < nk) copy_chunk(ci + 2, (ci + 2) % 3);

#pragma unroll
        for (int kk = 0; kk < 32; kk += 16) {
            uint32_t ah[2][4], al[2][4];
#pragma unroll
            for (int ms = 0; ms < 2; ms++) {
                uint32_t base = ((st * 2 + 0) * 128 + wm * 32 + ms * 16 + lrow) * 40
                                + kk + lcol8;
                ldsm4(ah[ms], sAaddr + base * 2);
                base = ((st * 2 + 1) * 128 + wm * 32 + ms * 16 + lrow) * 40 + kk + lcol8;
                ldsm4(al[ms], sAaddr + base * 2);
            }
            uint32_t bh01[4], bl01[4], bh23[4], bl23[4];
            {
                uint32_t b = ((st * 2 + 0) * 64 + wn * 32 + lrow) * 40 + kk + lcol8;
                ldsm4(bh01, sWaddr + b * 2);
                b = ((st * 2 + 1) * 64 + wn * 32 + lrow) * 40 + kk + lcol8;
                ldsm4(bl01, sWaddr + b * 2);
                b = ((st * 2 + 0) * 64 + wn * 32 + 16 + lrow) * 40 + kk + lcol8;
                ldsm4(bh23, sWaddr + b * 2);
                b = ((st * 2 + 1) * 64 + wn * 32 + 16 + lrow) * 40 + kk + lcol8;
                ldsm4(bl23, sWaddr + b * 2);
            }
#pragma unroll
            for (int ms = 0; ms < 2; ms++) {
                mma_bf16(acc[ms][0], ah[ms], bh01[0], bh01[2]);
                mma_bf16(acc[ms][0], ah[ms], bl01[0], bl01[2]);
                mma_bf16(acc[ms][0], al[ms], bh01[0], bh01[2]);
                mma_bf16(acc[ms][1], ah[ms], bh01[1], bh01[3]);
                mma_bf16(acc[ms][1], ah[ms], bl01[1], bl01[3]);
                mma_bf16(acc[ms][1], al[ms], bh01[1], bh01[3]);
                mma_bf16(acc[ms][2], ah[ms], bh23[0], bh23[2]);
                mma_bf16(acc[ms][2], ah[ms], bl23[0], bl23[2]);
                mma_bf16(acc[ms][2], al[ms], bh23[0], bh23[2]);
                mma_bf16(acc[ms][3], ah[ms], bh23[1], bh23[3]);
                mma_bf16(acc[ms][3], ah[ms], bl23[1], bl23[3]);
                mma_bf16(acc[ms][3], al[ms], bh23[1], bh23[3]);
            }
        }
    }

#pragma unroll
    for (int ms = 0; ms < 2; ms++)
#pragma unroll
        for (int nf = 0; nf < 4; nf++) {
            int col = n0 + wn * 32 + nf * 8 + tq * 2;
            float b0 = biasz ? biasz[col]     : 0.0f;
            float b1 = biasz ? biasz[col + 1] : 0.0f;
            int row = m0 + wm * 32 + ms * 16 + g;
            float* c0 = C + (size_t)row * N + col;
            c0[0] = acc[ms][nf][0] + b0;
            c0[1] = acc[ms][nf][1] + b1;
            float* c1 = C + (size_t)(row + 8) * N + col;
            c1[0] = acc[ms][nf][2] + b0;
            c1[1] = acc[ms][nf][3] + b1;
        }
}

// ----------------------------------------------------------------------------
// Grid barrier
// ----------------------------------------------------------------------------
__device__ __forceinline__ void grid_barrier() {
    __syncthreads();
    if (threadIdx.x == 0) {
        unsigned gen = g_bar_gen;
        __threadfence();
        if (atomicAdd(&g_bar_cnt, 1) == NRBLK - 1) {
            g_bar_cnt = 0;
            __threadfence();
            g_bar_gen = gen + 1;
        } else {
            while (g_bar_gen == gen) { __nanosleep(32); }
        }
        __threadfence();
    }
    __syncthreads();
}

// ----------------------------------------------------------------------------
// Gate-fused persistent recurrence. 128 blocks = 2 dirs x 64 tiles.
// Block owns 16 hidden cols (j0..j0+15): W rows (permuted) give r,z,n gates for
// exactly those cols -> gate update is a local epilogue. ONE barrier per step.
// smem: resident W hi/lo [48][SWPAD] + A ring [3][2][64][40] (C tile aliases A).
// ----------------------------------------------------------------------------
__global__ __launch_bounds__(256) void k_recur(
    const __nv_bfloat16* __restrict__ Whi,  // [2][G3][Hn] permuted rows
    const __nv_bfloat16* __restrict__ Wlo,
    const float* __restrict__ gi,           // [2][SB][G3]
    float* __restrict__ hcur,               // [2][B][H]
    __nv_bfloat16* __restrict__ hAhi,
    __nv_bfloat16* __restrict__ hAlo,
    const float* __restrict__ bhh_f, const float* __restrict__ bhh_b,
    __nv_bfloat16* __restrict__ h0hi,       // layer0: [2][SB][H]; else null
    __nv_bfloat16* __restrict__ h0lo,
    float* __restrict__ out)                // layer1: output; else null
{
    extern __shared__ __align__(16) char sm_raw[];
    __nv_bfloat16* sWhi = reinterpret_cast<__nv_bfloat16*>(sm_raw);
    __nv_bfloat16* sWlo = sWhi + RB * SWPAD;
    __nv_bfloat16* sAb  = sWlo + RB * SWPAD;           // [3][2][64][40]
    float* sC = reinterpret_cast<float*>(sAb);          // alias, [64][49]
    const uint32_t sAaddr  = (uint32_t)__cvta_generic_to_shared(sAb);
    const uint32_t sWhaddr = (uint32_t)__cvta_generic_to_shared(sWhi);
    const uint32_t sWladdr = (uint32_t)__cvta_generic_to_shared(sWlo);

    const int tid  = threadIdx.x;
    const int dir  = blockIdx.x >> 6;
    const int tile = blockIdx.x & 63;
    const int j0   = tile * 16;
    const int p0   = tile * RB;       // permuted W row base

    const __nv_bfloat16* WhiD = Whi + (size_t)dir * G3 * Hn;
    const __nv_bfloat16* WloD = Wlo + (size_t)dir * G3 * Hn;
    const __nv_bfloat16* AhiD = hAhi + (size_t)dir * Bn * Hn;
    const __nv_bfloat16* AloD = hAlo + (size_t)dir * Bn * Hn;
    const float* bhh = dir ? bhh_b : bhh_f;

    const int lane = tid & 31;
    const int warp = tid >> 5;
    const int wm = warp & 3;
    const int wn = warp >> 2;        // 0..1 -> 24 cols each
    const int g  = lane >> 2;
    const int tq = lane & 3;
    const int crow = tid >> 2;       // A copy row
    const int cq   = tid & 3;
    const int lrow   = lane & 15;
    const int lcol8  = (lane >> 4) * 8;
    const int lrow2  = lane & 7;
    const int lcol82 = ((lane >> 3) & 1) * 8;

    // gate-phase thread mapping
    const int gj = tid & 15;         // j' 0..15
    const int gb = tid >> 4;         // base batch row 0..15
    const float bias_n = bhh[2 * Hn + j0 + gj];

    // ---- load resident W slice (rows p0..p0+47) ----
    for (int i = tid; i < RB * (Hn / 8); i += 256) {
        int row = i >> 7;
        int q   = i & 127;
        const size_t off = (size_t)(p0 + row) * Hn + q * 8;
        cp16(&sWhi[row * SWPAD + q * 8], WhiD + off);
        cp16(&sWlo[row * SWPAD + q * 8], WloD + off);
    }
    CP_COMMIT();

    // ---- zero own state ----
    for (int i = tid; i < Bn * 16; i += 256) {
        int b = i >> 4, j = i & 15;
        int idx = dir * (Bn * Hn) + b * Hn + j0 + j;
        hcur[idx] = 0.0f;
        hAhi[idx] = __float2bfloat16(0.0f);
        hAlo[idx] = __float2bfloat16(0.0f);
    }
    CP_WAIT0();
    grid_barrier();

    auto copyA = [&](int ci, int st) {
        const size_t ao = (size_t)crow * Hn + ci * 32 + cq * 8;
        cp16(&sAb[((st * 2 + 0) * 64 + crow) * 40 + cq * 8], AhiD + ao);
        cp16(&sAb[((st * 2 + 1) * 64 + crow) * 40 + cq * 8], AloD + ao);
        CP_COMMIT();
    };

    for (int t = 0; t < Sn; ++t) {
        float acc[3][4];
#pragma unroll
        for (int i = 0; i < 3; i++)
#pragma unroll
            for (int j = 0; j < 4; j++) acc[i][j] = 0.0f;

        copyA(0, 0);
        copyA(1, 1);

        for (int ci = 0; ci < 32; ci++) {
            const int st = ci % 3;
            CP_WAIT1();
            __syncthreads();
            if (ci + 2 < 32) copyA(ci + 2, (ci + 2) % 3);

#pragma unroll
            for (int kk = 0; kk < 32; kk += 16) {
                const int kg = ci * 32 + kk;
                uint32_t ah[4], al[4];
                ldsm4(ah, sAaddr + (((st * 2 + 0) * 64 + wm * 16 + lrow) * 40 + kk + lcol8) * 2);
                ldsm4(al, sAaddr + (((st * 2 + 1) * 64 + wm * 16 + lrow) * 40 + kk + lcol8) * 2);
                uint32_t bh01[4], bl01[4], bh2[2], bl2[2];
                ldsm4(bh01, sWhaddr + ((wn * 24 + lrow) * SWPAD + kg + lcol8) * 2);
                ldsm4(bl01, sWladdr + ((wn * 24 + lrow) * SWPAD + kg + lcol8) * 2);
                ldsm2(bh2,  sWhaddr + ((wn * 24 + 16 + lrow2) * SWPAD + kg + lcol82) * 2);
                ldsm2(bl2,  sWladdr + ((wn * 24 + 16 + lrow2) * SWPAD + kg + lcol82) * 2);

                mma_bf16(acc[0], ah, bh01[0], bh01[2]);
                mma_bf16(acc[0], ah, bl01[0], bl01[2]);
                mma_bf16(acc[0], al, bh01[0], bh01[2]);
                mma_bf16(acc[1], ah, bh01[1], bh01[3]);
                mma_bf16(acc[1], ah, bl01[1], bl01[3]);
                mma_bf16(acc[1], al, bh01[1], bh01[3]);
                mma_bf16(acc[2], ah, bh2[0], bh2[1]);
                mma_bf16(acc[2], ah, bl2[0], bl2[1]);
                mma_bf16(acc[2], al, bh2[0], bh2[1]);
            }
        }

        // ---- epilogue: acc -> sC (aliases A ring; all reads done) ----
        __syncthreads();
#pragma unroll
        for (int nf = 0; nf < 3; nf++) {
            int col = wn * 24 + nf * 8 + tq * 2;
            int row = wm * 16 + g;
            sC[row * 49 + col]     = acc[nf][0];
            sC[row * 49 + col + 1] = acc[nf][1];
            sC[(row + 8) * 49 + col]     = acc[nf][2];
            sC[(row + 8) * 49 + col + 1] = acc[nf][3];
        }
        __syncthreads();

        // ---- gate update for own (dir, all b, j0+gj) ----
        const float* giT = gi + (size_t)dir * SB * G3 + (size_t)t * Bn * G3;
#pragma unroll
        for (int e = 0; e < 4; e++) {
            const int b = gb + e * 16;
            const float* gib = giT + (size_t)b * G3;
            float ir  = gib[j0 + gj];
            float iz  = gib[Hn + j0 + gj];
            float inn = gib[2 * Hn + j0 + gj];
            float hr  = sC[b * 49 + gj];
            float hz  = sC[b * 49 + 16 + gj];
            float hn  = sC[b * 49 + 32 + gj] + bias_n;
            const int idx = dir * (Bn * Hn) + b * Hn + j0 + gj;
            float h = hcur[idx];

            float r  = 1.0f / (1.0f + expf(-(ir + hr)));
            float zz = 1.0f / (1.0f + expf(-(iz + hz)));
            float n  = tanhf(inn + r * hn);
            float hnew = (1.0f - zz) * n + zz * h;

            hcur[idx] = hnew;
            __nv_bfloat16 hi = __float2bfloat16(hnew);
            __nv_bfloat16 lo = __float2bfloat16(hnew - __bfloat162float(hi));
            hAhi[idx] = hi;
            hAlo[idx] = lo;
            if (h0hi) {
                size_t o = (size_t)dir * SB * Hn + ((size_t)t * Bn + b) * Hn + j0 + gj;
                h0hi[o] = hi;
                h0lo[o] = lo;
            }
            if (out) {
                out[((size_t)b * Sn + t) * (2 * Hn) + (size_t)dir * Hn + j0 + gj] = hnew;
                if (t == Sn - 1)
                    out[(size_t)Bn * Sn * 2 * Hn + (size_t)b * 2 * Hn
                        + (size_t)dir * Hn + j0 + gj] = hnew;
            }
        }

        grid_barrier();
    }
}

// ----------------------------------------------------------------------------
// Launcher
// ----------------------------------------------------------------------------
extern "C" void kernel_launch(void* const* d_in, const int* in_sizes, int n_in,
                              void* d_out, int out_size) {
    const float* x      = (const float*)d_in[0];
    const float* w_ih0f = (const float*)d_in[1];
    const float* w_hh0f = (const float*)d_in[2];
    const float* b_ih0f = (const float*)d_in[3];
    const float* b_hh0f = (const float*)d_in[4];
    const float* w_ih0b = (const float*)d_in[5];
    const float* w_hh0b = (const float*)d_in[6];
    const float* b_ih0b = (const float*)d_in[7];
    const float* b_hh0b = (const float*)d_in[8];
    const float* w_ih1f = (const float*)d_in[9];
    const float* w_hh1f = (const float*)d_in[10];
    const float* b_ih1f = (const float*)d_in[11];
    const float* b_hh1f = (const float*)d_in[12];
    const float* w_ih1b = (const float*)d_in[13];
    const float* w_hh1b = (const float*)d_in[14];
    const float* b_ih1b = (const float*)d_in[15];
    const float* b_hh1b = (const float*)d_in[16];
    float* out = (float*)d_out;

    float *gi, *hcur, *bias0, *bias1;
    __nv_bfloat16 *xhi, *xlo, *h0hi, *h0lo, *hAhi, *hAlo;
    __nv_bfloat16 *wih0h, *wih0l, *whh0h, *whh0l, *wih1h, *wih1l, *whh1h, *whh1l;
    cudaGetSymbolAddress((void**)&xhi,   g_x_hi);
    cudaGetSymbolAddress((void**)&xlo,   g_x_lo);
    cudaGetSymbolAddress((void**)&gi,    g_gi);
    cudaGetSymbolAddress((void**)&h0hi,  g_h0_hi);
    cudaGetSymbolAddress((void**)&h0lo,  g_h0_lo);
    cudaGetSymbolAddress((void**)&hcur,  g_hcur);
    cudaGetSymbolAddress((void**)&hAhi,  g_hA_hi);
    cudaGetSymbolAddress((void**)&hAlo,  g_hA_lo);
    cudaGetSymbolAddress((void**)&bias0, g_bias0);
    cudaGetSymbolAddress((void**)&bias1, g_bias1);
    cudaGetSymbolAddress((void**)&wih0h, g_wih0_hi);
    cudaGetSymbolAddress((void**)&wih0l, g_wih0_lo);
    cudaGetSymbolAddress((void**)&whh0h, g_whh0_hi);
    cudaGetSymbolAddress((void**)&whh0l, g_whh0_lo);
    cudaGetSymbolAddress((void**)&wih1h, g_wih1_hi);
    cudaGetSymbolAddress((void**)&wih1l, g_wih1_lo);
    cudaGetSymbolAddress((void**)&whh1h, g_whh1_hi);
    cudaGetSymbolAddress((void**)&whh1l, g_whh1_lo);

    const int SMEM_RECUR = (2 * RB * SWPAD + 3 * 2 * 64 * 40) * (int)sizeof(__nv_bfloat16);
    const int SMEM_GEMM  = (3 * 2 * 128 * 40 + 3 * 2 * 64 * 40) * (int)sizeof(__nv_bfloat16);
    static bool attr_done = false;
    if (!attr_done) {
        cudaFuncSetAttribute(k_recur, cudaFuncAttributeMaxDynamicSharedMemorySize, SMEM_RECUR);
        cudaFuncSetAttribute(k_gemm,  cudaFuncAttributeMaxDynamicSharedMemorySize, SMEM_GEMM);
        attr_done = true;
    }

    // launch order chosen so ncu (-s 5) profiles the layer-1 k_recur
    k_prep<<<dim3(2048, 9), 256>>>(
        w_ih0f, w_ih0b, w_ih1f, w_ih1b, w_hh0f, w_hh0b, w_hh1f, w_hh1b,
        b_ih0f, b_hh0f, b_ih0b, b_hh0b, b_ih1f, b_hh1f, b_ih1b, b_hh1b);
    k_xT_split<<<2048, 256>>>(x, xhi, xlo);

    // layer 0: batched input projection (x shared across dirs)
    k_gemm<<<dim3(G3 / 64, SB / 128, 2), 256, SMEM_GEMM>>>(
        xhi, xlo, 0,
        wih0h, wih0l, (size_t)G3 * INn,
        bias0, G3, gi, (size_t)SB * G3, G3, INn);

    // layer 0 recurrence
    k_recur<<<NRBLK, 256, SMEM_RECUR>>>(
        whh0h, whh0l, gi, hcur, hAhi, hAlo,
        b_hh0f, b_hh0b, h0hi, h0lo, nullptr);

    // layer 1: batched input projection (per-dir A)
    k_gemm<<<dim3(G3 / 64, SB / 128, 2), 256, SMEM_GEMM>>>(
        h0hi, h0lo, (size_t)SB * Hn,
        wih1h, wih1l, (size_t)G3 * Hn,
        bias1, G3, gi, (size_t)SB * G3, G3, Hn);

    // layer 1 recurrence (writes output)
    k_recur<<<NRBLK, 256, SMEM_RECUR>>>(
        whh1h, whh1l, gi, hcur, hAhi, hAlo,
        b_hh1f, b_hh1b, nullptr, nullptr, out);
}

// round 6
// speedup vs baseline: 2.2540x; 1.3027x over previous
#include <cuda_runtime.h>
#include <cuda_bf16.h>
#include <stdint.h>
#include <math.h>

// Problem constants
#define Bn  64
#define Sn  512
#define INn 512
#define Hn  1024
#define G3  3072          // 3*H
#define SB  32768         // S*B

#define NRBLK 128         // recurrence grid: 2 dirs x 64 tiles (16 j-cols, 48 W rows)
#define NBAR  64          // barrier domain: blocks per direction
#define RB    48
#define SWPAD 1032        // resident W smem row stride (bf16 elems)
#define RTHREADS 512

// ----------------------------------------------------------------------------
// Device scratch (static — no allocations allowed)
// ----------------------------------------------------------------------------
__device__ __nv_bfloat16 g_x_hi[(size_t)SB * INn];
__device__ __nv_bfloat16 g_x_lo[(size_t)SB * INn];
__device__ float g_gi[(size_t)2 * SB * G3];
__device__ __nv_bfloat16 g_h0_hi[(size_t)2 * SB * Hn];
__device__ __nv_bfloat16 g_h0_lo[(size_t)2 * SB * Hn];
__device__ float g_hcur[2 * Bn * Hn];
__device__ __nv_bfloat16 g_hA_hi[2 * Bn * Hn];
__device__ __nv_bfloat16 g_hA_lo[2 * Bn * Hn];
__device__ float g_bias0[2 * G3];
__device__ float g_bias1[2 * G3];

__device__ __nv_bfloat16 g_wih0_hi[(size_t)2 * G3 * INn];
__device__ __nv_bfloat16 g_wih0_lo[(size_t)2 * G3 * INn];
__device__ __nv_bfloat16 g_wih1_hi[(size_t)2 * G3 * Hn];
__device__ __nv_bfloat16 g_wih1_lo[(size_t)2 * G3 * Hn];
// W_hh stored ROW-PERMUTED: row p = tile*48 + gate*16 + jj  <-  src row gate*H + tile*16 + jj
__device__ __nv_bfloat16 g_whh0_hi[(size_t)2 * G3 * Hn];
__device__ __nv_bfloat16 g_whh0_lo[(size_t)2 * G3 * Hn];
__device__ __nv_bfloat16 g_whh1_hi[(size_t)2 * G3 * Hn];
__device__ __nv_bfloat16 g_whh1_lo[(size_t)2 * G3 * Hn];

// per-direction barrier state
__device__ volatile unsigned g_bar_gen[2];
__device__ unsigned g_bar_cnt[2];

// ----------------------------------------------------------------------------
// cp.async / ldmatrix helpers
// ----------------------------------------------------------------------------
__device__ __forceinline__ void cp16(void* dst, const void* src) {
    uint32_t d = (uint32_t)__cvta_generic_to_shared(dst);
    asm volatile("cp.async.cg.shared.global [%0], [%1], 16;\n" :: "r"(d), "l"(src));
}
#define CP_COMMIT() asm volatile("cp.async.commit_group;\n")
#define CP_WAIT0()  asm volatile("cp.async.wait_group 0;\n")
#define CP_WAIT1()  asm volatile("cp.async.wait_group 1;\n")

__device__ __forceinline__ void ldsm4(uint32_t r[4], uint32_t saddr) {
    asm volatile("ldmatrix.sync.aligned.m8n8.x4.shared.b16 {%0,%1,%2,%3}, [%4];"
                 : "=r"(r[0]), "=r"(r[1]), "=r"(r[2]), "=r"(r[3]) : "r"(saddr));
}
__device__ __forceinline__ void ldsm2(uint32_t r[2], uint32_t saddr) {
    asm volatile("ldmatrix.sync.aligned.m8n8.x2.shared.b16 {%0,%1}, [%2];"
                 : "=r"(r[0]), "=r"(r[1]) : "r"(saddr));
}

__device__ __forceinline__ void mma_bf16(float c[4], const uint32_t a[4],
                                         uint32_t b0, uint32_t b1) {
    asm("mma.sync.aligned.m16n8k16.row.col.f32.bf16.bf16.f32 "
        "{%0,%1,%2,%3}, {%4,%5,%6,%7}, {%8,%9}, {%0,%1,%2,%3};\n"
        : "+f"(c[0]), "+f"(c[1]), "+f"(c[2]), "+f"(c[3])
        : "r"(a[0]), "r"(a[1]), "r"(a[2]), "r"(a[3]), "r"(b0), "r"(b1));
}

__device__ __forceinline__ float fsigmoid(float x) {
    return 1.0f / (1.0f + __expf(-x));
}

// ----------------------------------------------------------------------------
// Prep: all weight splits (+ W_hh permutation) + biases, one kernel
// ----------------------------------------------------------------------------
__device__ __forceinline__ void split_at(const float* src, size_t si,
                                         __nv_bfloat16* hi, __nv_bfloat16* lo, size_t di) {
    float v = src[si];
    __nv_bfloat16 h = __float2bfloat16(v);
    hi[di] = h;
    lo[di] = __float2bfloat16(v - __bfloat162float(h));
}

__global__ void k_prep(
    const float* __restrict__ wih0f, const float* __restrict__ wih0b,
    const float* __restrict__ wih1f, const float* __restrict__ wih1b,
    const float* __restrict__ whh0f, const float* __restrict__ whh0b,
    const float* __restrict__ whh1f, const float* __restrict__ whh1b,
    const float* __restrict__ bih0f, const float* __restrict__ bhh0f,
    const float* __restrict__ bih0b, const float* __restrict__ bhh0b,
    const float* __restrict__ bih1f, const float* __restrict__ bhh1f,
    const float* __restrict__ bih1b, const float* __restrict__ bhh1b)
{
    const int seg = blockIdx.y;
    const int stride = gridDim.x * blockDim.x;
    int i0 = blockIdx.x * blockDim.x + threadIdx.x;

    if (seg == 0) {
        for (int i = i0; i < G3 * INn; i += stride)
            split_at(wih0f, i, g_wih0_hi, g_wih0_lo, i);
    } else if (seg == 1) {
        for (int i = i0; i < G3 * INn; i += stride) {
            int n = i / INn, k = i % INn;
            split_at(wih0b, (size_t)n * INn + (INn - 1 - k),
                     g_wih0_hi, g_wih0_lo, (size_t)G3 * INn + i);
        }
    } else if (seg == 2) {
        for (int i = i0; i < G3 * Hn; i += stride)
            split_at(wih1f, i, g_wih1_hi, g_wih1_lo, i);
    } else if (seg == 3) {
        for (int i = i0; i < G3 * Hn; i += stride)
            split_at(wih1b, i, g_wih1_hi, g_wih1_lo, (size_t)G3 * Hn + i);
    } else if (seg <= 7) {
        const float* src = (seg == 4) ? whh0f : (seg == 5) ? whh0b
                         : (seg == 6) ? whh1f : whh1b;
        __nv_bfloat16* hi = (seg <= 5) ? g_whh0_hi : g_whh1_hi;
        __nv_bfloat16* lo = (seg <= 5) ? g_whh0_lo : g_whh1_lo;
        size_t doff = (seg == 5 || seg == 7) ? (size_t)G3 * Hn : 0;
        for (int i = i0; i < G3 * Hn; i += stride) {
            int prow = i >> 10, k = i & 1023;
            int tile = prow / 48, gate = (prow % 48) >> 4, jj = prow & 15;
            size_t srow = (size_t)gate * Hn + tile * 16 + jj;
            split_at(src, srow * Hn + k, hi, lo, doff + i);
        }
    } else {
        for (int i = i0; i < G3; i += stride) {
            float add = (i < 2 * Hn) ? 1.0f : 0.0f;
            g_bias0[i]      = bih0f[i] + add * bhh0f[i];
            g_bias0[G3 + i] = bih0b[i] + add * bhh0b[i];
            g_bias1[i]      = bih1f[i] + add * bhh1f[i];
            g_bias1[G3 + i] = bih1b[i] + add * bhh1b[i];
        }
    }
}

__global__ void k_xT_split(const float* __restrict__ x,
                           __nv_bfloat16* __restrict__ hi,
                           __nv_bfloat16* __restrict__ lo) {
    size_t total = (size_t)Bn * Sn * INn;
    for (size_t i = (size_t)blockIdx.x * blockDim.x + threadIdx.x; i < total;
         i += (size_t)gridDim.x * blockDim.x) {
        int k = (int)(i % INn);
        size_t tmp = i / INn;
        int s = (int)(tmp % Sn);
        int b = (int)(tmp / Sn);
        float v = x[i];
        __nv_bfloat16 h = __float2bfloat16(v);
        size_t o = ((size_t)s * Bn + b) * INn + k;
        hi[o] = h;
        lo[o] = __float2bfloat16(v - __bfloat162float(h));
    }
}

// ----------------------------------------------------------------------------
// Batched split-bf16 GEMM, 128x64 tile, 3-stage cp.async, ldmatrix fragments.
// ----------------------------------------------------------------------------
__global__ __launch_bounds__(256) void k_gemm(
    const __nv_bfloat16* __restrict__ Ahi, const __nv_bfloat16* __restrict__ Alo,
    size_t aStrZ,
    const __nv_bfloat16* __restrict__ Whi, const __nv_bfloat16* __restrict__ Wlo,
    size_t wStrZ,
    const float* __restrict__ bias, size_t bStrZ,
    float* __restrict__ C, size_t cStrZ,
    int N, int K)
{
    const int z = blockIdx.z;
    Ahi += (size_t)z * aStrZ;  Alo += (size_t)z * aStrZ;
    Whi += (size_t)z * wStrZ;  Wlo += (size_t)z * wStrZ;
    const float* biasz = bias ? (bias + (size_t)z * bStrZ) : nullptr;
    C += (size_t)z * cStrZ;

    const int m0 = blockIdx.y * 128;
    const int n0 = blockIdx.x * 64;

    extern __shared__ __align__(16) __nv_bfloat16 sm[];
    __nv_bfloat16* sA = sm;                     // [3][2][128][40]
    __nv_bfloat16* sW = sm + 3 * 2 * 128 * 40;  // [3][2][64][40]
    const uint32_t sAaddr = (uint32_t)__cvta_generic_to_shared(sA);
    const uint32_t sWaddr = (uint32_t)__cvta_generic_to_shared(sW);

    const int tid  = threadIdx.x;
    const int lane = tid & 31;
    const int warp = tid >> 5;
    const int wm = warp & 3;
    const int wn = warp >> 2;
    const int g  = lane >> 2;
    const int tq = lane & 3;

    const int arow = tid >> 1;
    const int acol = (tid & 1) * 16;
    const int wrow = tid >> 2;
    const int wcol = (tid & 3) * 8;
    const int lrow  = lane & 15;
    const int lcol8 = (lane >> 4) * 8;

    float acc[2][4][4];
#pragma unroll
    for (int a = 0; a < 2; a++)
#pragma unroll
        for (int b = 0; b < 4; b++)
#pragma unroll
            for (int c = 0; c < 4; c++) acc[a][b][c] = 0.0f;

    const int nk = K / 32;

    auto copy_chunk = [&](int ci, int st) {
        const int k0 = ci * 32;
        const size_t ao = (size_t)(m0 + arow) * K + k0 + acol;
        __nv_bfloat16* dA0 = sA + ((st * 2 + 0) * 128 + arow) * 40 + acol;
        __nv_bfloat16* dA1 = sA + ((st * 2 + 1) * 128 + arow) * 40 + acol;
        cp16(dA0,     Ahi + ao);
        cp16(dA0 + 8, Ahi + ao + 8);
        cp16(dA1,     Alo + ao);
        cp16(dA1 + 8, Alo + ao + 8);
        const size_t wo = (size_t)(n0 + wrow) * K + k0 + wcol;
        cp16(sW + ((st * 2 + 0) * 64 + wrow) * 40 + wcol, Whi + wo);
        cp16(sW + ((st * 2 + 1) * 64 + wrow) * 40 + wcol, Wlo + wo);
        CP_COMMIT();
    };

    copy_chunk(0, 0);
    copy_chunk(1, 1);

    for (int ci = 0; ci < nk; ci++) {
        const int st = ci % 3;
        CP_WAIT1();
        __syncthreads();
        if (ci + 2 < nk) copy_chunk(ci + 2, (ci + 2) % 3);
        else CP_COMMIT();   // empty group keeps wait_group accounting correct

#pragma unroll
        for (int kk = 0; kk < 32; kk += 16) {
            uint32_t ah[2][4], al[2][4];
#pragma unroll
            for (int ms = 0; ms < 2; ms++) {
                uint32_t base = ((st * 2 + 0) * 128 + wm * 32 + ms * 16 + lrow) * 40
                                + kk + lcol8;
                ldsm4(ah[ms], sAaddr + base * 2);
                base = ((st * 2 + 1) * 128 + wm * 32 + ms * 16 + lrow) * 40 + kk + lcol8;
                ldsm4(al[ms], sAaddr + base * 2);
            }
            uint32_t bh01[4], bl01[4], bh23[4], bl23[4];
            {
                uint32_t b = ((st * 2 + 0) * 64 + wn * 32 + lrow) * 40 + kk + lcol8;
                ldsm4(bh01, sWaddr + b * 2);
                b = ((st * 2 + 1) * 64 + wn * 32 + lrow) * 40 + kk + lcol8;
                ldsm4(bl01, sWaddr + b * 2);
                b = ((st * 2 + 0) * 64 + wn * 32 + 16 + lrow) * 40 + kk + lcol8;
                ldsm4(bh23, sWaddr + b * 2);
                b = ((st * 2 + 1) * 64 + wn * 32 + 16 + lrow) * 40 + kk + lcol8;
                ldsm4(bl23, sWaddr + b * 2);
            }
#pragma unroll
            for (int ms = 0; ms < 2; ms++) {
                mma_bf16(acc[ms][0], ah[ms], bh01[0], bh01[2]);
                mma_bf16(acc[ms][0], ah[ms], bl01[0], bl01[2]);
                mma_bf16(acc[ms][0], al[ms], bh01[0], bh01[2]);
                mma_bf16(acc[ms][1], ah[ms], bh01[1], bh01[3]);
                mma_bf16(acc[ms][1], ah[ms], bl01[1], bl01[3]);
                mma_bf16(acc[ms][1], al[ms], bh01[1], bh01[3]);
                mma_bf16(acc[ms][2], ah[ms], bh23[0], bh23[2]);
                mma_bf16(acc[ms][2], ah[ms], bl23[0], bl23[2]);
                mma_bf16(acc[ms][2], al[ms], bh23[0], bh23[2]);
                mma_bf16(acc[ms][3], ah[ms], bh23[1], bh23[3]);
                mma_bf16(acc[ms][3], ah[ms], bl23[1], bl23[3]);
                mma_bf16(acc[ms][3], al[ms], bh23[1], bh23[3]);
            }
        }
    }

#pragma unroll
    for (int ms = 0; ms < 2; ms++)
#pragma unroll
        for (int nf = 0; nf < 4; nf++) {
            int col = n0 + wn * 32 + nf * 8 + tq * 2;
            float b0 = biasz ? biasz[col]     : 0.0f;
            float b1 = biasz ? biasz[col + 1] : 0.0f;
            int row = m0 + wm * 32 + ms * 16 + g;
            float* c0 = C + (size_t)row * N + col;
            c0[0] = acc[ms][nf][0] + b0;
            c0[1] = acc[ms][nf][1] + b1;
            float* c1 = C + (size_t)(row + 8) * N + col;
            c1[0] = acc[ms][nf][2] + b0;
            c1[1] = acc[ms][nf][3] + b1;
        }
}

// ----------------------------------------------------------------------------
// Per-direction grid barrier (64 blocks per domain)
// ----------------------------------------------------------------------------
__device__ __forceinline__ void grid_barrier(int dir) {
    __syncthreads();
    if (threadIdx.x == 0) {
        unsigned gen = g_bar_gen[dir];
        __threadfence();
        if (atomicAdd(&g_bar_cnt[dir], 1) == NBAR - 1) {
            g_bar_cnt[dir] = 0;
            __threadfence();
            g_bar_gen[dir] = gen + 1;
        } else {
            while (g_bar_gen[dir] == gen) { __nanosleep(32); }
        }
        __threadfence();
    }
    __syncthreads();
}

// ----------------------------------------------------------------------------
// Gate-fused persistent recurrence, 512 threads (16 warps).
// Warps: wk (K16-slice of chunk) x wm (16 M rows) x wn (24 W cols).
// Partial accs reduced through two smem C buffers. ONE barrier/step, per dir.
// ----------------------------------------------------------------------------
__global__ __launch_bounds__(RTHREADS) void k_recur(
    const __nv_bfloat16* __restrict__ Whi,  // [2][G3][Hn] permuted rows
    const __nv_bfloat16* __restrict__ Wlo,
    const float* __restrict__ gi,           // [2][SB][G3]
    float* __restrict__ hcur,               // [2][B][H]
    __nv_bfloat16* __restrict__ hAhi,
    __nv_bfloat16* __restrict__ hAlo,
    const float* __restrict__ bhh_f, const float* __restrict__ bhh_b,
    __nv_bfloat16* __restrict__ h0hi,       // layer0: [2][SB][H]; else null
    __nv_bfloat16* __restrict__ h0lo,
    float* __restrict__ out)                // layer1: output; else null
{
    extern __shared__ __align__(16) char sm_raw[];
    __nv_bfloat16* sWhi = reinterpret_cast<__nv_bfloat16*>(sm_raw);
    __nv_bfloat16* sWlo = sWhi + RB * SWPAD;
    __nv_bfloat16* sAb  = sWlo + RB * SWPAD;           // [3][2][64][40]
    float* sC = reinterpret_cast<float*>(sAb);          // alias, [2][64][49]
    const uint32_t sAaddr  = (uint32_t)__cvta_generic_to_shared(sAb);
    const uint32_t sWhaddr = (uint32_t)__cvta_generic_to_shared(sWhi);
    const uint32_t sWladdr = (uint32_t)__cvta_generic_to_shared(sWlo);

    const int tid  = threadIdx.x;
    const int dir  = blockIdx.x >> 6;
    const int tile = blockIdx.x & 63;
    const int j0   = tile * 16;
    const int p0   = tile * RB;

    const __nv_bfloat16* WhiD = Whi + (size_t)dir * G3 * Hn;
    const __nv_bfloat16* WloD = Wlo + (size_t)dir * G3 * Hn;
    const __nv_bfloat16* AhiD = hAhi + (size_t)dir * Bn * Hn;
    const __nv_bfloat16* AloD = hAlo + (size_t)dir * Bn * Hn;
    const float* bhh = dir ? bhh_b : bhh_f;

    const int lane = tid & 31;
    const int warp = tid >> 5;
    const int wk = warp >> 3;        // K16 slice of chunk: kk = wk*16
    const int w8 = warp & 7;
    const int wm = w8 & 3;           // 16 M rows
    const int wn = w8 >> 2;          // 24 W cols
    const int kk = wk * 16;
    const int g  = lane >> 2;
    const int tq = lane & 3;
    const int lrow   = lane & 15;
    const int lcol8  = (lane >> 4) * 8;
    const int lrow2  = lane & 7;
    const int lcol82 = ((lane >> 3) & 1) * 8;

    // A-copy mapping: 512 threads, one cp16 each per chunk
    const int cp_p = tid >> 8;             // plane hi/lo
    const int cp_r = (tid >> 2) & 63;      // row
    const int cp_q = tid & 3;              // 8-elem chunk

    // gate-phase mapping
    const int gj = tid & 15;
    const int gb = tid >> 4;               // 0..31
    const float bias_n = bhh[2 * Hn + j0 + gj];

    // ---- load resident W slice ----
    for (int i = tid; i < RB * (Hn / 8); i += RTHREADS) {
        int row = i >> 7;
        int q   = i & 127;
        const size_t off = (size_t)(p0 + row) * Hn + q * 8;
        cp16(&sWhi[row * SWPAD + q * 8], WhiD + off);
        cp16(&sWlo[row * SWPAD + q * 8], WloD + off);
    }
    CP_COMMIT();

    // ---- zero own state ----
    for (int i = tid; i < Bn * 16; i += RTHREADS) {
        int b = i >> 4, j = i & 15;
        int idx = dir * (Bn * Hn) + b * Hn + j0 + j;
        hcur[idx] = 0.0f;
        hAhi[idx] = __float2bfloat16(0.0f);
        hAlo[idx] = __float2bfloat16(0.0f);
    }
    CP_WAIT0();
    grid_barrier(dir);

    auto copyA = [&](int ci, int st) {
        const __nv_bfloat16* src = cp_p ? AloD : AhiD;
        cp16(&sAb[((st * 2 + cp_p) * 64 + cp_r) * 40 + cp_q * 8],
             src + (size_t)cp_r * Hn + ci * 32 + cp_q * 8);
        CP_COMMIT();
    };

    for (int t = 0; t < Sn; ++t) {
        float acc[3][4];
#pragma unroll
        for (int i = 0; i < 3; i++)
#pragma unroll
            for (int j = 0; j < 4; j++) acc[i][j] = 0.0f;

        copyA(0, 0);
        copyA(1, 1);

        for (int ci = 0; ci < 32; ci++) {
            const int st = ci % 3;
            CP_WAIT1();
            __syncthreads();
            if (ci + 2 < 32) copyA(ci + 2, (ci + 2) % 3);
            else CP_COMMIT();   // empty group: wait accounting stays exact

            const int kg = ci * 32 + kk;
            uint32_t ah[4], al[4];
            ldsm4(ah, sAaddr + (((st * 2 + 0) * 64 + wm * 16 + lrow) * 40 + kk + lcol8) * 2);
            ldsm4(al, sAaddr + (((st * 2 + 1) * 64 + wm * 16 + lrow) * 40 + kk + lcol8) * 2);
            uint32_t bh01[4], bl01[4], bh2[2], bl2[2];
            ldsm4(bh01, sWhaddr + ((wn * 24 + lrow) * SWPAD + kg + lcol8) * 2);
            ldsm4(bl01, sWladdr + ((wn * 24 + lrow) * SWPAD + kg + lcol8) * 2);
            ldsm2(bh2,  sWhaddr + ((wn * 24 + 16 + lrow2) * SWPAD + kg + lcol82) * 2);
            ldsm2(bl2,  sWladdr + ((wn * 24 + 16 + lrow2) * SWPAD + kg + lcol82) * 2);

            mma_bf16(acc[0], ah, bh01[0], bh01[2]);
            mma_bf16(acc[0], ah, bl01[0], bl01[2]);
            mma_bf16(acc[0], al, bh01[0], bh01[2]);
            mma_bf16(acc[1], ah, bh01[1], bh01[3]);
            mma_bf16(acc[1], ah, bl01[1], bl01[3]);
            mma_bf16(acc[1], al, bh01[1], bh01[3]);
            mma_bf16(acc[2], ah, bh2[0], bh2[1]);
            mma_bf16(acc[2], ah, bl2[0], bl2[1]);
            mma_bf16(acc[2], al, bh2[0], bh2[1]);
        }

        // ---- epilogue: partial accs -> two sC buffers (alias A ring) ----
        __syncthreads();
        {
            float* sCw = sC + wk * (64 * 49);
#pragma unroll
            for (int nf = 0; nf < 3; nf++) {
                int col = wn * 24 + nf * 8 + tq * 2;
                int row = wm * 16 + g;
                sCw[row * 49 + col]     = acc[nf][0];
                sCw[row * 49 + col + 1] = acc[nf][1];
                sCw[(row + 8) * 49 + col]     = acc[nf][2];
                sCw[(row + 8) * 49 + col + 1] = acc[nf][3];
            }
        }
        __syncthreads();

        // ---- gate update for own (dir, all b, j0+gj) ----
        const float* giT = gi + (size_t)dir * SB * G3 + (size_t)t * Bn * G3;
#pragma unroll
        for (int e = 0; e < 2; e++) {
            const int b = gb + e * 32;
            const float* gib = giT + (size_t)b * G3;
            const float* c0 = sC + b * 49;
            const float* c1 = sC + 64 * 49 + b * 49;
            float ir  = gib[j0 + gj];
            float iz  = gib[Hn + j0 + gj];
            float inn = gib[2 * Hn + j0 + gj];
            float hr  = c0[gj]          + c1[gj];
            float hz  = c0[16 + gj]     + c1[16 + gj];
            float hn  = c0[32 + gj]     + c1[32 + gj] + bias_n;
            const int idx = dir * (Bn * Hn) + b * Hn + j0 + gj;
            float h = hcur[idx];

            float r  = fsigmoid(ir + hr);
            float zz = fsigmoid(iz + hz);
            float n  = tanhf(inn + r * hn);
            float hnew = (1.0f - zz) * n + zz * h;

            hcur[idx] = hnew;
            __nv_bfloat16 hi = __float2bfloat16(hnew);
            __nv_bfloat16 lo = __float2bfloat16(hnew - __bfloat162float(hi));
            hAhi[idx] = hi;
            hAlo[idx] = lo;
            if (h0hi) {
                size_t o = (size_t)dir * SB * Hn + ((size_t)t * Bn + b) * Hn + j0 + gj;
                h0hi[o] = hi;
                h0lo[o] = lo;
            }
            if (out) {
                out[((size_t)b * Sn + t) * (2 * Hn) + (size_t)dir * Hn + j0 + gj] = hnew;
                if (t == Sn - 1)
                    out[(size_t)Bn * Sn * 2 * Hn + (size_t)b * 2 * Hn
                        + (size_t)dir * Hn + j0 + gj] = hnew;
            }
        }

        grid_barrier(dir);
    }
}

// ----------------------------------------------------------------------------
// Launcher
// ----------------------------------------------------------------------------
extern "C" void kernel_launch(void* const* d_in, const int* in_sizes, int n_in,
                              void* d_out, int out_size) {
    const float* x      = (const float*)d_in[0];
    const float* w_ih0f = (const float*)d_in[1];
    const float* w_hh0f = (const float*)d_in[2];
    const float* b_ih0f = (const float*)d_in[3];
    const float* b_hh0f = (const float*)d_in[4];
    const float* w_ih0b = (const float*)d_in[5];
    const float* w_hh0b = (const float*)d_in[6];
    const float* b_ih0b = (const float*)d_in[7];
    const float* b_hh0b = (const float*)d_in[8];
    const float* w_ih1f = (const float*)d_in[9];
    const float* w_hh1f = (const float*)d_in[10];
    const float* b_ih1f = (const float*)d_in[11];
    const float* b_hh1f = (const float*)d_in[12];
    const float* w_ih1b = (const float*)d_in[13];
    const float* w_hh1b = (const float*)d_in[14];
    const float* b_ih1b = (const float*)d_in[15];
    const float* b_hh1b = (const float*)d_in[16];
    float* out = (float*)d_out;

    float *gi, *hcur, *bias0, *bias1;
    __nv_bfloat16 *xhi, *xlo, *h0hi, *h0lo, *hAhi, *hAlo;
    __nv_bfloat16 *wih0h, *wih0l, *whh0h, *whh0l, *wih1h, *wih1l, *whh1h, *whh1l;
    cudaGetSymbolAddress((void**)&xhi,   g_x_hi);
    cudaGetSymbolAddress((void**)&xlo,   g_x_lo);
    cudaGetSymbolAddress((void**)&gi,    g_gi);
    cudaGetSymbolAddress((void**)&h0hi,  g_h0_hi);
    cudaGetSymbolAddress((void**)&h0lo,  g_h0_lo);
    cudaGetSymbolAddress((void**)&hcur,  g_hcur);
    cudaGetSymbolAddress((void**)&hAhi,  g_hA_hi);
    cudaGetSymbolAddress((void**)&hAlo,  g_hA_lo);
    cudaGetSymbolAddress((void**)&bias0, g_bias0);
    cudaGetSymbolAddress((void**)&bias1, g_bias1);
    cudaGetSymbolAddress((void**)&wih0h, g_wih0_hi);
    cudaGetSymbolAddress((void**)&wih0l, g_wih0_lo);
    cudaGetSymbolAddress((void**)&whh0h, g_whh0_hi);
    cudaGetSymbolAddress((void**)&whh0l, g_whh0_lo);
    cudaGetSymbolAddress((void**)&wih1h, g_wih1_hi);
    cudaGetSymbolAddress((void**)&wih1l, g_wih1_lo);
    cudaGetSymbolAddress((void**)&whh1h, g_whh1_hi);
    cudaGetSymbolAddress((void**)&whh1l, g_whh1_lo);

    const int SMEM_RECUR = (2 * RB * SWPAD + 3 * 2 * 64 * 40) * (int)sizeof(__nv_bfloat16);
    const int SMEM_GEMM  = (3 * 2 * 128 * 40 + 3 * 2 * 64 * 40) * (int)sizeof(__nv_bfloat16);
    static bool attr_done = false;
    if (!attr_done) {
        cudaFuncSetAttribute(k_recur, cudaFuncAttributeMaxDynamicSharedMemorySize, SMEM_RECUR);
        cudaFuncSetAttribute(k_gemm,  cudaFuncAttributeMaxDynamicSharedMemorySize, SMEM_GEMM);
        attr_done = true;
    }

    k_prep<<<dim3(2048, 9), 256>>>(
        w_ih0f, w_ih0b, w_ih1f, w_ih1b, w_hh0f, w_hh0b, w_hh1f, w_hh1b,
        b_ih0f, b_hh0f, b_ih0b, b_hh0b, b_ih1f, b_hh1f, b_ih1b, b_hh1b);
    k_xT_split<<<2048, 256>>>(x, xhi, xlo);

    // layer 0: batched input projection (x shared across dirs)
    k_gemm<<<dim3(G3 / 64, SB / 128, 2), 256, SMEM_GEMM>>>(
        xhi, xlo, 0,
        wih0h, wih0l, (size_t)G3 * INn,
        bias0, G3, gi, (size_t)SB * G3, G3, INn);

    // layer 0 recurrence
    k_recur<<<NRBLK, RTHREADS, SMEM_RECUR>>>(
        whh0h, whh0l, gi, hcur, hAhi, hAlo,
        b_hh0f, b_hh0b, h0hi, h0lo, nullptr);

    // layer 1: batched input projection (per-dir A)
    k_gemm<<<dim3(G3 / 64, SB / 128, 2), 256, SMEM_GEMM>>>(
        h0hi, h0lo, (size_t)SB * Hn,
        wih1h, wih1l, (size_t)G3 * Hn,
        bias1, G3, gi, (size_t)SB * G3, G3, Hn);

    // layer 1 recurrence (writes output)
    k_recur<<<NRBLK, RTHREADS, SMEM_RECUR>>>(
        whh1h, whh1l, gi, hcur, hAhi, hAlo,
        b_hh1f, b_hh1b, nullptr, nullptr, out);
}